// round 11
// baseline (speedup 1.0000x reference)
#include <cuda_runtime.h>
#include <cuda_fp16.h>
#include <math.h>

#define EPSF 1e-8f
#define NBC 64
#define NN 20
#define LPB 21
#define TPB (LPB*32)

// weights region (floats)
static constexpr int OW0 = 0, OW1 = 976, OW2 = 5136, OB0 = 5200, OB1 = 5264, OMISC = 5328, WFL = 5336;
// per-lane offsets (floats)
static constexpr int LNDN = 0, LNOR = 60, LNEWR = 240, LP = 240, LFCR = 260, LGO = 260,
    LSO = 280, LZ = 290, LENC = LZ, LGZ = 310, LGPRE = 330, LSC = 350,
    // mid region (1280 fl), lifetime-aliased: DRW/RR/SEL -> FEAT -> ga2 -> ga1
    LDRW = 352, LRR = 544, LSEL = 608, LFEAT = 352, LGT = 352,
    // fp16 h1 tile (64 rows x 20 halves = 640 fl), then GF (320 fl) over dead h1
    LH1H = 1632, LGF = 1632, LANE_F = 2272;
static constexpr int SMEM_FLOATS = WFL + LPB * LANE_F;   // 53048 fl = 212192 B

typedef unsigned long long u64;
__device__ __forceinline__ u64 pk2(float a){ u64 r; asm("mov.b64 %0, {%1, %1};":"=l"(r):"f"(a)); return r; }
__device__ __forceinline__ u64 pk(float a,float b){ u64 r; asm("mov.b64 %0, {%1, %2};":"=l"(r):"f"(a),"f"(b)); return r; }
__device__ __forceinline__ void upk(u64 v,float&a,float&b){ asm("mov.b64 {%0, %1}, %2;":"=f"(a),"=f"(b):"l"(v)); }
__device__ __forceinline__ void fma2(u64&c,u64 a,u64 b){ asm("fma.rn.f32x2 %0, %1, %2, %0;":"+l"(c):"l"(a),"l"(b)); }
__device__ __forceinline__ u64 fma2o(u64 a,u64 b,u64 c){ u64 d; asm("fma.rn.f32x2 %0, %1, %2, %3;":"=l"(d):"l"(a),"l"(b),"l"(c)); return d; }
__device__ __forceinline__ u64 mul2(u64 a,u64 b){ u64 d; asm("mul.rn.f32x2 %0, %1, %2;":"=l"(d):"l"(a),"l"(b)); return d; }
__device__ __forceinline__ u64 add2(u64 a,u64 b){ u64 d; asm("add.rn.f32x2 %0, %1, %2;":"=l"(d):"l"(a),"l"(b)); return d; }
__device__ __forceinline__ float ex2a(float x){ float r; asm("ex2.approx.f32 %0, %1;":"=f"(r):"f"(x)); return r; }
__device__ __forceinline__ float lg2a(float x){ float r; asm("lg2.approx.f32 %0, %1;":"=f"(r):"f"(x)); return r; }
__device__ __forceinline__ float rcpa(float x){ float r; asm("rcp.approx.f32 %0, %1;":"=f"(r):"f"(x)); return r; }
__device__ __forceinline__ float tanhfst(float x){
    float e = ex2a(x * 2.885390082f);
    return fmaf(-2.0f, rcpa(e + 1.0f), 1.0f);
}
__device__ __forceinline__ u64 tanh2(u64 v){ float a,b; upk(v,a,b); return pk(tanhfst(a), tanhfst(b)); }
// fp16x2 <-> packed f32x2
__device__ __forceinline__ unsigned int h2pack(u64 v){
    float a,b; upk(v,a,b);
    __half2 h = __floats2half2_rn(a,b);
    return *(unsigned int*)&h;
}
__device__ __forceinline__ u64 h2unpack(unsigned int hv){
    __half2 h = *(__half2*)&hv;
    float2 f = __half22float2(h);
    return pk(f.x, f.y);
}

__global__ __launch_bounds__(TPB, 1)
void ep_kernel(const float* __restrict__ dr, const float* __restrict__ orientation,
               const float* __restrict__ n_or,
               const float* __restrict__ W0, const float* __restrict__ b0,
               const float* __restrict__ W1, const float* __restrict__ b1,
               const float* __restrict__ W2, const float* __restrict__ b2,
               const float* __restrict__ f1, const float* __restrict__ f2,
               float* __restrict__ out, int B)
{
    extern __shared__ float sm[];
    const int tid = threadIdx.x;
    for (int idx = tid; idx < 960; idx += TPB)  { int i=idx>>6, j=idx&63; sm[OW0+i*65+j]=W0[idx]; }
    for (int idx = tid; idx < 4096; idx += TPB) { int k=idx>>6, j=idx&63; sm[OW1+k*65+j]=W1[idx]; }
    if (tid < 64) { sm[OW2+tid]=W2[tid]; sm[OB0+tid]=b0[tid]; sm[OB1+tid]=b1[tid]; }
    if (tid == 0) {
        sm[OMISC] = b2[0];
        #pragma unroll
        for (int j = 0; j < 3; j++) {
            float a=f1[j]; sm[OMISC+1+j]=a*a+EPSF;
            float p=f2[j]; sm[OMISC+4+j]=p*p+EPSF;
        }
    }
    __syncthreads();

    const int li = tid >> 5, t = tid & 31;
    const int s = t & 15, half = t >> 4;
    const int batch0 = blockIdx.x * LPB + li;
    const bool wr = batch0 < B;
    const int batch = wr ? batch0 : 0;
    float* L = sm + WFL + li * LANE_F;
    int* selp = (int*)(L + LSEL);
    unsigned int* H1 = (unsigned int*)(L + LH1H);   // row j: 10 u32 (20 halves)

    // A: stage dr + orientation
    {
        const float4* src = (const float4*)(dr + (size_t)batch * 192);
        float4* dst = (float4*)(L + LDRW);
        dst[t] = src[t];
        if (t < 16) dst[t+32] = src[t+32];
        if (t < 9) L[LSO+t] = orientation[(size_t)batch*9 + t];
    }
    __syncwarp();
    // B: radii
    #pragma unroll
    for (int c = 0; c < 2; c++) {
        int u = 2*t+c;
        float x=L[LDRW+u*3]+EPSF, y=L[LDRW+u*3+1]+EPSF, z=L[LDRW+u*3+2]+EPSF;
        L[LRR+u] = sqrtf(x*x+y*y+z*z);
    }
    __syncwarp();
    // C: stable rank
    {
        float Ru[2]; int rk[2];
        #pragma unroll
        for (int c=0;c<2;c++){ Ru[c]=L[LRR+2*t+c]; rk[c]=0; }
        const float4* R4 = (const float4*)(L + LRR);
        #pragma unroll 4
        for (int v4=0; v4<16; v4++){
            float4 rv = R4[v4]; int v = 4*v4;
            #pragma unroll
            for (int c=0;c<2;c++){
                int u = 2*t+c;
                rk[c] += (rv.x<Ru[c])||(rv.x==Ru[c]&&v  <u);
                rk[c] += (rv.y<Ru[c])||(rv.y==Ru[c]&&v+1<u);
                rk[c] += (rv.z<Ru[c])||(rv.z==Ru[c]&&v+2<u);
                rk[c] += (rv.w<Ru[c])||(rv.w==Ru[c]&&v+3<u);
            }
        }
        #pragma unroll
        for (int c=0;c<2;c++) if (rk[c] < NN) selp[rk[c]] = 2*t+c;
    }
    __syncwarp();
    // D: gather top-20
    if (t < NN) {
        int u = selp[t];
        float Rv = L[LRR+u];
        L[LNEWR+t] = Rv;
        float inv = 1.0f / Rv;
        L[LNDN+t*3+0] = (L[LDRW+u*3+0]+EPSF)*inv;
        L[LNDN+t*3+1] = (L[LDRW+u*3+1]+EPSF)*inv;
        L[LNDN+t*3+2] = (L[LDRW+u*3+2]+EPSF)*inv;
        L[LFCR+t] = (Rv > 4.8f) ? 0.0f : (0.5f*cospif(Rv*(1.0f/4.8f)) + 0.5f);
        const float* np_ = n_or + ((size_t)batch*NBC + u)*9;
        #pragma unroll
        for (int e = 0; e < 9; e++) L[LNOR+t*9+e] = np_[e];
    }
    __syncwarp();
    // E: features featT[i][n], stride 20 (over dead DRW/RR/SEL)
    {
        int n = (t * 0x8889) >> 19;
        int i = t - n*15;
        #pragma unroll
        for (int it = 0; it < 10; it++) {
            int p = t + 32*it;
            if (p < 300) {
                const float* nd = L+LNDN+n*3; const float* NO = L+LNOR+n*9; const float* O = L+LSO;
                float v;
                if (i < 3)      v = nd[0]*O[i]   + nd[1]*O[3+i]   + nd[2]*O[6+i];
                else if (i < 6){ int h=i-3; v = nd[0]*NO[h] + nd[1]*NO[3+h] + nd[2]*NO[6+h]; }
                else { int l=(i-6)/3, m=(i-6)%3; v = O[l]*NO[m] + O[3+l]*NO[3+m] + O[6+l]*NO[6+m]; }
                L[LFEAT + i*20 + n] = v;
            }
            n += 2; i += 2;
            if (i >= 15) { i -= 15; n += 1; }
        }
    }
    __syncwarp();

    u64 acc[20];
    // F: GEMM1 -> h1 (fp16 store)
    #pragma unroll
    for (int i=0;i<4;i++){ u64 bb=pk2(sm[OB0+s+16*i]);
        #pragma unroll
        for (int q=0;q<5;q++) acc[i*5+q]=bb; }
    #pragma unroll 5
    for (int k=0;k<15;k++){
        u64 wA=pk2(sm[OW0+k*65+s]),    wB=pk2(sm[OW0+k*65+s+16]);
        u64 wC=pk2(sm[OW0+k*65+s+32]), wD=pk2(sm[OW0+k*65+s+48]);
        const u64* ap=(const u64*)(L+LFEAT+k*20) + 5*half;
        #pragma unroll
        for (int q=0;q<5;q++){ u64 av=ap[q];
            fma2(acc[q],wA,av); fma2(acc[5+q],wB,av);
            fma2(acc[10+q],wC,av); fma2(acc[15+q],wD,av); }
    }
    #pragma unroll
    for (int i=0;i<4;i++){
        unsigned int* hr = H1 + (s+16*i)*10 + 5*half;
        #pragma unroll
        for (int q=0;q<5;q++) hr[q] = h2pack(tanh2(acc[i*5+q]));
    }
    __syncwarp();
    // G: GEMM2 -> h2 (registers only); acts fp16
    #pragma unroll
    for (int i=0;i<4;i++){ u64 bb=pk2(sm[OB1+s+16*i]);
        #pragma unroll
        for (int q=0;q<5;q++) acc[i*5+q]=bb; }
    #pragma unroll 8
    for (int k=0;k<64;k++){
        u64 wA=pk2(sm[OW1+k*65+s]),    wB=pk2(sm[OW1+k*65+s+16]);
        u64 wC=pk2(sm[OW1+k*65+s+32]), wD=pk2(sm[OW1+k*65+s+48]);
        const unsigned int* ap = H1 + k*10 + 5*half;
        #pragma unroll
        for (int q=0;q<5;q++){ u64 av=h2unpack(ap[q]);
            fma2(acc[q],wA,av); fma2(acc[5+q],wB,av);
            fma2(acc[10+q],wC,av); fma2(acc[15+q],wD,av); }
    }
    #pragma unroll
    for (int v=0; v<20; v++) acc[v] = tanh2(acc[v]);

    // H: z reduction, enc, prior
    {
        u64 zp[5];
        #pragma unroll
        for (int q=0;q<5;q++) zp[q]=0ull;
        #pragma unroll
        for (int i=0;i<4;i++){ u64 w2p=pk2(sm[OW2+s+16*i]);
            #pragma unroll
            for (int q=0;q<5;q++) fma2(zp[q], w2p, acc[i*5+q]); }
        #pragma unroll
        for (int m=1;m<16;m<<=1){
            #pragma unroll
            for (int q=0;q<5;q++) zp[q]=add2(zp[q], __shfl_xor_sync(0xffffffffu, zp[q], m));
        }
        if (s==0){ u64 b2p=pk2(sm[OMISC]); u64* zz=(u64*)(L+LZ) + 5*half;
            #pragma unroll
            for (int q=0;q<5;q++) zz[q]=add2(zp[q],b2p); }
    }
    __syncwarp();
    if (t < NN){
        float enc = tanhfst(L[LZ+t]);
        float e = enc*enc + EPSF;
        float Rm = L[LNEWR+t] - e;
        float P=0.f, D=0.f;
        #pragma unroll
        for (int j=0;j<3;j++){
            float a=sm[OMISC+1+j], p=sm[OMISC+4+j];
            float tt = ex2a(-p * lg2a(a*Rm));
            P += tt; D += p*tt;
        }
        L[LP+t]=P; L[LGPRE+t]=D/Rm; L[LENC+t]=enc;
    }
    __syncwarp();
    if (t==0){
        float S=0.f, F=0.f;
        #pragma unroll
        for (int n=0;n<NN;n++){ S+=L[LP+n]; F+=L[LFCR+n]; }
        L[LSC]=S; L[LSC+1]=F;
    }
    __syncwarp();
    if (t < NN){
        float enc=L[LENC+t];
        L[LGZ+t] = L[LSC+1]*L[LGPRE+t]*2.f*enc*(1.f-enc*enc);
        if (wr) out[(size_t)6*B + (size_t)batch*NN + t] = L[LSC]*L[LFCR+t];
    }
    __syncwarp();
    // I: ga2 from register h2 -> smem (LGT over dead feat)
    {
        const u64 SGN = 0x8000000080000000ULL;
        u64 one2 = pk2(1.0f);
        #pragma unroll
        for (int i=0;i<4;i++){
            u64 w2p=pk2(sm[OW2+s+16*i]);
            u64* gr=(u64*)(L+LGT+(s+16*i)*20) + 5*half;
            #pragma unroll
            for (int q=0;q<5;q++){
                u64 h2v=acc[i*5+q];
                u64 d = fma2o(h2v ^ SGN, h2v, one2);
                u64 gzq = *(const u64*)(L+LGZ+2*(5*half+q));
                gr[q] = mul2(mul2(gzq,w2p), d);
            }
        }
    }
    __syncwarp();
    // J: GEMM3 (gh1 = ga2 @ W1^T); then ga1 (fp32) OVERWRITES ga2 region
    #pragma unroll
    for (int v=0; v<20; v++) acc[v]=0ull;
    #pragma unroll 8
    for (int k=0;k<64;k++){
        u64 wA=pk2(sm[OW1+ s      *65+k]), wB=pk2(sm[OW1+(s+16)*65+k]);
        u64 wC=pk2(sm[OW1+(s+32)*65+k]),   wD=pk2(sm[OW1+(s+48)*65+k]);
        const u64* ap=(const u64*)(L+LGT+k*20) + 5*half;
        #pragma unroll
        for (int q=0;q<5;q++){ u64 av=ap[q];
            fma2(acc[q],wA,av); fma2(acc[5+q],wB,av);
            fma2(acc[10+q],wC,av); fma2(acc[15+q],wD,av); }
    }
    __syncwarp();   // all ga2 reads complete before overwrite
    {
        const u64 SGN = 0x8000000080000000ULL;
        u64 one2 = pk2(1.0f);
        #pragma unroll
        for (int i=0;i<4;i++){
            const unsigned int* hr = H1 + (s+16*i)*10 + 5*half;
            u64* gr=(u64*)(L+LGT+(s+16*i)*20) + 5*half;
            #pragma unroll
            for (int q=0;q<5;q++){
                u64 h1v = h2unpack(hr[q]);
                u64 d = fma2o(h1v ^ SGN, h1v, one2);
                gr[q] = mul2(acc[i*5+q], d);
            }
        }
    }
    __syncwarp();
    // K: GEMM4 gfeat[n][i] = sum_k ga1[k][n] W0[i][k]; GF over dead fp16 h1
    if (s < 15){
        u64 a4[5];
        #pragma unroll
        for (int q=0;q<5;q++) a4[q]=0ull;
        #pragma unroll 8
        for (int k=0;k<64;k++){
            u64 w=pk2(sm[OW0+s*65+k]);
            const u64* ap=(const u64*)(L+LGT+k*20) + 5*half;
            #pragma unroll
            for (int q=0;q<5;q++) fma2(a4[q],w,ap[q]);
        }
        #pragma unroll
        for (int q=0;q<5;q++){
            float lo,hi; upk(a4[q],lo,hi);
            int n0 = 10*half + 2*q;
            L[LGF+n0*16+s]=lo; L[LGF+(n0+1)*16+s]=hi;
        }
    }
    __syncwarp();
    // L: force, gO (aliases dead LFCR), torque
    if (t < 3){
        float f=0.f; const float* O=L+LSO;
        for (int n=0;n<NN;n++){
            const float* g=L+LGF+n*16; const float* NO=L+LNOR+n*9;
            f += g[0]*O[t*3]+g[1]*O[t*3+1]+g[2]*O[t*3+2];
            f += g[3]*NO[t*3]+g[4]*NO[t*3+1]+g[5]*NO[t*3+2];
        }
        if (wr) out[(size_t)batch*3+t]=f;
    }
    if (t >= 4 && t < 13){
        int a=(t-4)/3, bb=(t-4)%3; float g2=0.f;
        for (int n=0;n<NN;n++){
            const float* g=L+LGF+n*16; const float* NO=L+LNOR+n*9;
            g2 += L[LNDN+n*3+a]*g[bb];
            g2 += g[6+3*bb+0]*NO[a*3+0]+g[6+3*bb+1]*NO[a*3+1]+g[6+3*bb+2]*NO[a*3+2];
        }
        L[LGO+a*3+bb]=g2;
    }
    __syncwarp();
    if (t==0 && wr){
        const float* gO=L+LGO; const float* O=L+LSO;
        float tx=0.f,ty=0.f,tz=0.f;
        #pragma unroll
        for (int c=0;c<3;c++){
            float u0=gO[c],u1=gO[3+c],u2=gO[6+c];
            float v0=O[c], v1=O[3+c], v2=O[6+c];
            tx += u1*v2-u2*v1; ty += u2*v0-u0*v2; tz += u0*v1-u1*v0;
        }
        out[(size_t)3*B+(size_t)batch*3+0]=tx;
        out[(size_t)3*B+(size_t)batch*3+1]=ty;
        out[(size_t)3*B+(size_t)batch*3+2]=tz;
    }
}

extern "C" void kernel_launch(void* const* d_in, const int* in_sizes, int n_in,
                              void* d_out, int out_size) {
    const float* dr  = (const float*)d_in[0];
    const float* ori = (const float*)d_in[1];
    const float* nor = (const float*)d_in[2];
    const float* W0  = (const float*)d_in[3];
    const float* b0  = (const float*)d_in[4];
    const float* W1  = (const float*)d_in[5];
    const float* b1  = (const float*)d_in[6];
    const float* W2  = (const float*)d_in[7];
    const float* b2  = (const float*)d_in[8];
    const float* f1  = (const float*)d_in[9];
    const float* f2  = (const float*)d_in[10];
    float* out = (float*)d_out;

    int B = in_sizes[0] / (NBC * 3);
    int blocks = (B + LPB - 1) / LPB;
    size_t shmem = (size_t)SMEM_FLOATS * sizeof(float);
    cudaFuncSetAttribute(ep_kernel, cudaFuncAttributeMaxDynamicSharedMemorySize, (int)shmem);
    ep_kernel<<<blocks, TPB, shmem>>>(dr, ori, nor, W0, b0, W1, b1, W2, b2, f1, f2, out, B);
}

// round 12
// speedup vs baseline: 1.6894x; 1.6894x over previous
#include <cuda_runtime.h>
#include <cuda_fp16.h>
#include <math.h>

#define EPSF 1e-8f
#define NBC 64
#define NN 20
#define LPB 18
#define TPB (LPB*32)

// block weights (floats)
static constexpr int OW0 = 0, OW2 = 976, OB0 = 1040, OB1 = 1104, OMISC = 1168;
static constexpr int OW1H = 1176;    // fp16 W1 [k][j] stride 72 halves = 2304 fl
static constexpr int OW1HT = 3480;   // fp16 W1^T [j][k] stride 72 halves = 2304 fl
static constexpr int WFL = 5784;
// per-lane (floats)
static constexpr int LNDN = 0, LNOR = 60, LNEWR = 240, LP = 240, LFCR = 260, LGO = 260,
    LSO = 280, LZ = 292 /*24*/, LENC = LZ, LGZ = 316 /*24*/, LGPRE = 340, LSC = 360,
    // region A (1280 fl): DRW/RR/SEL -> FEAT -> ga2T(fp16) -> ga1(fp32)
    LDRW = 368, LRR = 560, LSEL = 624, LFEAT = 368, LGA2 = 368, LGT = 368,
    // region B (864 fl): h1T fp16 [24][72] -> GF
    LH1T = 1648, LGF = 1648, LANE_F = 2512;
static constexpr int SMEM_FLOATS = WFL + LPB * LANE_F;   // 51000 fl = 204000 B

typedef unsigned long long u64;
typedef unsigned int u32;
__device__ __forceinline__ u64 pk2(float a){ u64 r; asm("mov.b64 %0, {%1, %1};":"=l"(r):"f"(a)); return r; }
__device__ __forceinline__ u64 pk(float a,float b){ u64 r; asm("mov.b64 %0, {%1, %2};":"=l"(r):"f"(a),"f"(b)); return r; }
__device__ __forceinline__ void upk(u64 v,float&a,float&b){ asm("mov.b64 {%0, %1}, %2;":"=f"(a),"=f"(b):"l"(v)); }
__device__ __forceinline__ void fma2(u64&c,u64 a,u64 b){ asm("fma.rn.f32x2 %0, %1, %2, %0;":"+l"(c):"l"(a),"l"(b)); }
__device__ __forceinline__ float ex2a(float x){ float r; asm("ex2.approx.f32 %0, %1;":"=f"(r):"f"(x)); return r; }
__device__ __forceinline__ float lg2a(float x){ float r; asm("lg2.approx.f32 %0, %1;":"=f"(r):"f"(x)); return r; }
__device__ __forceinline__ float rcpa(float x){ float r; asm("rcp.approx.f32 %0, %1;":"=f"(r):"f"(x)); return r; }
__device__ __forceinline__ float tanhfst(float x){
    float e = ex2a(x * 2.885390082f);
    return fmaf(-2.0f, rcpa(e + 1.0f), 1.0f);
}
__device__ __forceinline__ void hmma(float&d0,float&d1,float&d2,float&d3,
                                     u32 a0,u32 a1,u32 a2,u32 a3,u32 b0,u32 b1){
    asm volatile("mma.sync.aligned.m16n8k16.row.col.f32.f16.f16.f32 "
                 "{%0,%1,%2,%3},{%4,%5,%6,%7},{%8,%9},{%0,%1,%2,%3};"
                 : "+f"(d0),"+f"(d1),"+f"(d2),"+f"(d3)
                 : "r"(a0),"r"(a1),"r"(a2),"r"(a3),"r"(b0),"r"(b1));
}

__global__ __launch_bounds__(TPB, 1)
void ep_kernel(const float* __restrict__ dr, const float* __restrict__ orientation,
               const float* __restrict__ n_or,
               const float* __restrict__ W0, const float* __restrict__ b0,
               const float* __restrict__ W1, const float* __restrict__ b1,
               const float* __restrict__ W2, const float* __restrict__ b2,
               const float* __restrict__ f1, const float* __restrict__ f2,
               float* __restrict__ out, int B)
{
    extern __shared__ float sm[];
    const int tid = threadIdx.x;
    for (int idx = tid; idx < 960; idx += TPB)  { int i=idx>>6, j=idx&63; sm[OW0+i*65+j]=W0[idx]; }
    {
        __half* w1h  = (__half*)(sm+OW1H);
        __half* w1ht = (__half*)(sm+OW1HT);
        for (int idx = tid; idx < 4096; idx += TPB) {
            int k=idx>>6, j=idx&63; __half hv=__float2half(W1[idx]);
            w1h[k*72+j]=hv; w1ht[j*72+k]=hv;
        }
    }
    if (tid < 64) { sm[OW2+tid]=W2[tid]; sm[OB0+tid]=b0[tid]; sm[OB1+tid]=b1[tid]; }
    if (tid == 0) {
        sm[OMISC] = b2[0];
        #pragma unroll
        for (int j = 0; j < 3; j++) {
            float a=f1[j]; sm[OMISC+1+j]=a*a+EPSF;
            float p=f2[j]; sm[OMISC+4+j]=p*p+EPSF;
        }
    }
    __syncthreads();

    const u32* W1h32  = (const u32*)(sm+OW1H);
    const u32* W1hT32 = (const u32*)(sm+OW1HT);

    const int li = tid >> 5, t = tid & 31;
    const int s = t & 15, half = t >> 4;      // SIMT GEMM mapping
    const int g = t >> 2, tg = t & 3;         // MMA fragment mapping
    const int batch0 = blockIdx.x * LPB + li;
    const bool wr = batch0 < B;
    const int batch = wr ? batch0 : 0;
    float* L = sm + WFL + li * LANE_F;
    int* selp = (int*)(L + LSEL);
    __half* H1Th = (__half*)(L + LH1T);
    u32*    H1T32 = (u32*)(L + LH1T);
    __half* GA2h = (__half*)(L + LGA2);
    const u32* GA2_32 = (const u32*)(L + LGA2);

    // A: stage dr + orientation
    {
        const float4* src = (const float4*)(dr + (size_t)batch * 192);
        float4* dst = (float4*)(L + LDRW);
        dst[t] = src[t];
        if (t < 16) dst[t+32] = src[t+32];
        if (t < 9) L[LSO+t] = orientation[(size_t)batch*9 + t];
    }
    __syncwarp();
    // B: radii
    #pragma unroll
    for (int c = 0; c < 2; c++) {
        int u = 2*t+c;
        float x=L[LDRW+u*3]+EPSF, y=L[LDRW+u*3+1]+EPSF, z=L[LDRW+u*3+2]+EPSF;
        L[LRR+u] = sqrtf(x*x+y*y+z*z);
    }
    __syncwarp();
    // C: stable rank
    {
        float Ru[2]; int rk[2];
        #pragma unroll
        for (int c=0;c<2;c++){ Ru[c]=L[LRR+2*t+c]; rk[c]=0; }
        const float4* R4 = (const float4*)(L + LRR);
        #pragma unroll 4
        for (int v4=0; v4<16; v4++){
            float4 rv = R4[v4]; int v = 4*v4;
            #pragma unroll
            for (int c=0;c<2;c++){
                int u = 2*t+c;
                rk[c] += (rv.x<Ru[c])||(rv.x==Ru[c]&&v  <u);
                rk[c] += (rv.y<Ru[c])||(rv.y==Ru[c]&&v+1<u);
                rk[c] += (rv.z<Ru[c])||(rv.z==Ru[c]&&v+2<u);
                rk[c] += (rv.w<Ru[c])||(rv.w==Ru[c]&&v+3<u);
            }
        }
        #pragma unroll
        for (int c=0;c<2;c++) if (rk[c] < NN) selp[rk[c]] = 2*t+c;
    }
    __syncwarp();
    // D: gather top-20
    if (t < NN) {
        int u = selp[t];
        float Rv = L[LRR+u];
        L[LNEWR+t] = Rv;
        float inv = 1.0f / Rv;
        L[LNDN+t*3+0] = (L[LDRW+u*3+0]+EPSF)*inv;
        L[LNDN+t*3+1] = (L[LDRW+u*3+1]+EPSF)*inv;
        L[LNDN+t*3+2] = (L[LDRW+u*3+2]+EPSF)*inv;
        L[LFCR+t] = (Rv > 4.8f) ? 0.0f : (0.5f*cospif(Rv*(1.0f/4.8f)) + 0.5f);
        const float* np_ = n_or + ((size_t)batch*NBC + u)*9;
        #pragma unroll
        for (int e = 0; e < 9; e++) L[LNOR+t*9+e] = np_[e];
    }
    __syncwarp();
    // E: features featT[i][n] stride 20 (over dead DRW/RR/SEL)
    {
        int n = (t * 0x8889) >> 19;
        int i = t - n*15;
        #pragma unroll
        for (int it = 0; it < 10; it++) {
            int p = t + 32*it;
            if (p < 300) {
                const float* nd = L+LNDN+n*3; const float* NO = L+LNOR+n*9; const float* O = L+LSO;
                float v;
                if (i < 3)      v = nd[0]*O[i]   + nd[1]*O[3+i]   + nd[2]*O[6+i];
                else if (i < 6){ int h=i-3; v = nd[0]*NO[h] + nd[1]*NO[3+h] + nd[2]*NO[6+h]; }
                else { int l=(i-6)/3, m=(i-6)%3; v = O[l]*NO[m] + O[3+l]*NO[3+m] + O[6+l]*NO[6+m]; }
                L[LFEAT + i*20 + n] = v;
            }
            n += 2; i += 2;
            if (i >= 15) { i -= 15; n += 1; }
        }
    }
    __syncwarp();

    // F: GEMM1 (SIMT fp32) -> h1 stored fp16 TRANSPOSED [n][k] stride 72 halves
    {
        u64 acc[20];
        #pragma unroll
        for (int i=0;i<4;i++){ u64 bb=pk2(sm[OB0+s+16*i]);
            #pragma unroll
            for (int q=0;q<5;q++) acc[i*5+q]=bb; }
        #pragma unroll 5
        for (int k=0;k<15;k++){
            u64 wA=pk2(sm[OW0+k*65+s]),    wB=pk2(sm[OW0+k*65+s+16]);
            u64 wC=pk2(sm[OW0+k*65+s+32]), wD=pk2(sm[OW0+k*65+s+48]);
            const u64* ap=(const u64*)(L+LFEAT+k*20) + 5*half;
            #pragma unroll
            for (int q=0;q<5;q++){ u64 av=ap[q];
                fma2(acc[q],wA,av); fma2(acc[5+q],wB,av);
                fma2(acc[10+q],wC,av); fma2(acc[15+q],wD,av); }
        }
        #pragma unroll
        for (int i=0;i<4;i++){
            int j = s + 16*i;
            #pragma unroll
            for (int q=0;q<5;q++){
                float lo,hi; upk(acc[i*5+q],lo,hi);
                int n0 = 10*half + 2*q;
                H1Th[ n0   *72 + j] = __float2half(tanhfst(lo));
                H1Th[(n0+1)*72 + j] = __float2half(tanhfst(hi));
            }
        }
        // zero pad rows n=20..23 (u32 720..863)
        for (int idx=t; idx<144; idx+=32) H1T32[720+idx] = 0u;
    }
    __syncwarp();

    // Bias/w2 fragment scalars
    float b1g[4], b1g8[4], w2g[4], w2g8[4];
    #pragma unroll
    for (int mt=0; mt<4; mt++){
        b1g[mt]  = sm[OB1 + mt*16 + g];
        b1g8[mt] = sm[OB1 + mt*16 + g + 8];
        w2g[mt]  = sm[OW2 + mt*16 + g];
        w2g8[mt] = sm[OW2 + mt*16 + g + 8];
    }

    // G: GEMM2 via mma.sync: d[nt][mt][c] = b1 + W1^T @ h1   (j = M, k = K, n = N)
    float d[3][4][4];
    #pragma unroll
    for (int nt=0; nt<3; nt++)
        #pragma unroll
        for (int mt=0; mt<4; mt++){
            d[nt][mt][0]=b1g[mt]; d[nt][mt][1]=b1g[mt];
            d[nt][mt][2]=b1g8[mt]; d[nt][mt][3]=b1g8[mt];
        }
    #pragma unroll
    for (int kt=0; kt<4; kt++){
        u32 A0[4],A1[4],A2[4],A3[4];
        #pragma unroll
        for (int mt=0; mt<4; mt++){
            int base = (mt*16+g)*36 + kt*8 + tg;
            A0[mt]=W1hT32[base];       A1[mt]=W1hT32[base+288];
            A2[mt]=W1hT32[base+4];     A3[mt]=W1hT32[base+292];
        }
        #pragma unroll
        for (int nt=0; nt<3; nt++){
            int bb = (nt*8+g)*36 + kt*8 + tg;
            u32 bf0 = H1T32[bb], bf1 = H1T32[bb+4];
            #pragma unroll
            for (int mt=0; mt<4; mt++)
                hmma(d[nt][mt][0],d[nt][mt][1],d[nt][mt][2],d[nt][mt][3],
                     A0[mt],A1[mt],A2[mt],A3[mt],bf0,bf1);
        }
    }
    #pragma unroll
    for (int nt=0; nt<3; nt++)
        #pragma unroll
        for (int mt=0; mt<4; mt++)
            #pragma unroll
            for (int c=0;c<4;c++) d[nt][mt][c] = tanhfst(d[nt][mt][c]);

    // H1: z[n] = b2 + sum_j w2[j] h2[j][n] via fragment butterfly
    {
        float zp0[3], zp1[3];
        #pragma unroll
        for (int nt=0; nt<3; nt++){
            float p0=0.f, p1=0.f;
            #pragma unroll
            for (int mt=0; mt<4; mt++){
                p0 += w2g[mt]*d[nt][mt][0] + w2g8[mt]*d[nt][mt][2];
                p1 += w2g[mt]*d[nt][mt][1] + w2g8[mt]*d[nt][mt][3];
            }
            zp0[nt]=p0; zp1[nt]=p1;
        }
        #pragma unroll
        for (int m=4;m<32;m<<=1){
            #pragma unroll
            for (int nt=0; nt<3; nt++){
                zp0[nt] += __shfl_xor_sync(0xffffffffu, zp0[nt], m);
                zp1[nt] += __shfl_xor_sync(0xffffffffu, zp1[nt], m);
            }
        }
        if (g==0){
            float b2v = sm[OMISC];
            #pragma unroll
            for (int nt=0; nt<3; nt++){
                float2 v; v.x = zp0[nt]+b2v; v.y = zp1[nt]+b2v;
                *(float2*)(L + LZ + nt*8 + 2*tg) = v;
            }
        }
    }
    __syncwarp();
    // H2: enc, prior per n
    if (t < NN){
        float enc = tanhfst(L[LZ+t]);
        float e = enc*enc + EPSF;
        float Rm = L[LNEWR+t] - e;
        float P=0.f, D=0.f;
        #pragma unroll
        for (int j=0;j<3;j++){
            float a=sm[OMISC+1+j], p=sm[OMISC+4+j];
            float tt = ex2a(-p * lg2a(a*Rm));
            P += tt; D += p*tt;
        }
        L[LP+t]=P; L[LGPRE+t]=D/Rm; L[LENC+t]=enc;
    }
    __syncwarp();
    if (t==0){
        float S=0.f, F=0.f;
        #pragma unroll
        for (int n=0;n<NN;n++){ S+=L[LP+n]; F+=L[LFCR+n]; }
        L[LSC]=S; L[LSC+1]=F;
    }
    __syncwarp();
    if (t < NN){
        float enc=L[LENC+t];
        L[LGZ+t] = L[LSC+1]*L[LGPRE+t]*2.f*enc*(1.f-enc*enc);
        if (wr) out[(size_t)6*B + (size_t)batch*NN + t] = L[LSC]*L[LFCR+t];
    } else if (t < 24) {
        L[LGZ+t] = 0.f;
    }
    __syncwarp();
    // I: ga2 = gz[n]*w2[j]*(1-h2^2) -> fp16 [n][j] stride 72 (over dead FEAT)
    #pragma unroll
    for (int nt=0; nt<3; nt++){
        float2 gz2 = *(const float2*)(L + LGZ + nt*8 + 2*tg);
        int n0 = nt*8 + 2*tg;
        #pragma unroll
        for (int mt=0; mt<4; mt++){
            int j0 = mt*16 + g;
            float v00 = gz2.x * w2g[mt]  * (1.f - d[nt][mt][0]*d[nt][mt][0]);
            float v01 = gz2.y * w2g[mt]  * (1.f - d[nt][mt][1]*d[nt][mt][1]);
            float v02 = gz2.x * w2g8[mt] * (1.f - d[nt][mt][2]*d[nt][mt][2]);
            float v03 = gz2.y * w2g8[mt] * (1.f - d[nt][mt][3]*d[nt][mt][3]);
            GA2h[ n0   *72 + j0  ] = __float2half(v00);
            GA2h[(n0+1)*72 + j0  ] = __float2half(v01);
            GA2h[ n0   *72 + j0+8] = __float2half(v02);
            GA2h[(n0+1)*72 + j0+8] = __float2half(v03);
        }
    }
    __syncwarp();
    // J: GEMM3 via mma.sync: gh1[k][n] = W1 @ ga2  (k = M, j = K, n = N)
    float e3[3][4][4];
    #pragma unroll
    for (int nt=0; nt<3; nt++)
        #pragma unroll
        for (int mt=0; mt<4; mt++)
            #pragma unroll
            for (int c=0;c<4;c++) e3[nt][mt][c]=0.f;
    #pragma unroll
    for (int kt=0; kt<4; kt++){
        u32 A0[4],A1[4],A2[4],A3[4];
        #pragma unroll
        for (int mt=0; mt<4; mt++){
            int base = (mt*16+g)*36 + kt*8 + tg;
            A0[mt]=W1h32[base];       A1[mt]=W1h32[base+288];
            A2[mt]=W1h32[base+4];     A3[mt]=W1h32[base+292];
        }
        #pragma unroll
        for (int nt=0; nt<3; nt++){
            int bb = (nt*8+g)*36 + kt*8 + tg;
            u32 bf0 = GA2_32[bb], bf1 = GA2_32[bb+4];
            #pragma unroll
            for (int mt=0; mt<4; mt++)
                hmma(e3[nt][mt][0],e3[nt][mt][1],e3[nt][mt][2],e3[nt][mt][3],
                     A0[mt],A1[mt],A2[mt],A3[mt],bf0,bf1);
        }
    }
    __syncwarp();
    // ga1 = gh1*(1-h1^2) -> fp32 [k][n] stride 20 (overwrites ga2T region)
    #pragma unroll
    for (int nt=0; nt<3; nt++){
        int n0 = nt*8 + 2*tg;
        if (n0 < 20){
            #pragma unroll
            for (int mt=0; mt<4; mt++){
                int k = mt*16 + g;
                float h00 = __half2float(H1Th[ n0   *72 + k]);
                float h01 = __half2float(H1Th[(n0+1)*72 + k]);
                float2 v0; v0.x = e3[nt][mt][0]*(1.f-h00*h00);
                           v0.y = e3[nt][mt][1]*(1.f-h01*h01);
                *(float2*)(L + LGT + k*20 + n0) = v0;
                int k8 = k + 8;
                float h10 = __half2float(H1Th[ n0   *72 + k8]);
                float h11 = __half2float(H1Th[(n0+1)*72 + k8]);
                float2 v1; v1.x = e3[nt][mt][2]*(1.f-h10*h10);
                           v1.y = e3[nt][mt][3]*(1.f-h11*h11);
                *(float2*)(L + LGT + k8*20 + n0) = v1;
            }
        }
    }
    __syncwarp();
    // K: GEMM4 (SIMT fp32) gfeat[n][i] = sum_k ga1[k][n] W0[i][k]; GF over dead h1T
    if (s < 15){
        u64 a4[5];
        #pragma unroll
        for (int q=0;q<5;q++) a4[q]=0ull;
        #pragma unroll 8
        for (int k=0;k<64;k++){
            u64 w=pk2(sm[OW0+s*65+k]);
            const u64* ap=(const u64*)(L+LGT+k*20) + 5*half;
            #pragma unroll
            for (int q=0;q<5;q++) fma2(a4[q],w,ap[q]);
        }
        #pragma unroll
        for (int q=0;q<5;q++){
            float lo,hi; upk(a4[q],lo,hi);
            int n0 = 10*half + 2*q;
            L[LGF+n0*16+s]=lo; L[LGF+(n0+1)*16+s]=hi;
        }
    }
    __syncwarp();
    // L: force, gO, torque
    if (t < 3){
        float f=0.f; const float* O=L+LSO;
        for (int n=0;n<NN;n++){
            const float* gg=L+LGF+n*16; const float* NO=L+LNOR+n*9;
            f += gg[0]*O[t*3]+gg[1]*O[t*3+1]+gg[2]*O[t*3+2];
            f += gg[3]*NO[t*3]+gg[4]*NO[t*3+1]+gg[5]*NO[t*3+2];
        }
        if (wr) out[(size_t)batch*3+t]=f;
    }
    if (t >= 4 && t < 13){
        int a=(t-4)/3, bb=(t-4)%3; float g2=0.f;
        for (int n=0;n<NN;n++){
            const float* gg=L+LGF+n*16; const float* NO=L+LNOR+n*9;
            g2 += L[LNDN+n*3+a]*gg[bb];
            g2 += gg[6+3*bb+0]*NO[a*3+0]+gg[6+3*bb+1]*NO[a*3+1]+gg[6+3*bb+2]*NO[a*3+2];
        }
        L[LGO+a*3+bb]=g2;
    }
    __syncwarp();
    if (t==0 && wr){
        const float* gO=L+LGO; const float* O=L+LSO;
        float tx=0.f,ty=0.f,tz=0.f;
        #pragma unroll
        for (int c=0;c<3;c++){
            float u0=gO[c],u1=gO[3+c],u2=gO[6+c];
            float v0=O[c], v1=O[3+c], v2=O[6+c];
            tx += u1*v2-u2*v1; ty += u2*v0-u0*v2; tz += u0*v1-u1*v0;
        }
        out[(size_t)3*B+(size_t)batch*3+0]=tx;
        out[(size_t)3*B+(size_t)batch*3+1]=ty;
        out[(size_t)3*B+(size_t)batch*3+2]=tz;
    }
}

extern "C" void kernel_launch(void* const* d_in, const int* in_sizes, int n_in,
                              void* d_out, int out_size) {
    const float* dr  = (const float*)d_in[0];
    const float* ori = (const float*)d_in[1];
    const float* nor = (const float*)d_in[2];
    const float* W0  = (const float*)d_in[3];
    const float* b0  = (const float*)d_in[4];
    const float* W1  = (const float*)d_in[5];
    const float* b1  = (const float*)d_in[6];
    const float* W2  = (const float*)d_in[7];
    const float* b2  = (const float*)d_in[8];
    const float* f1  = (const float*)d_in[9];
    const float* f2  = (const float*)d_in[10];
    float* out = (float*)d_out;

    int B = in_sizes[0] / (NBC * 3);
    int blocks = (B + LPB - 1) / LPB;
    size_t shmem = (size_t)SMEM_FLOATS * sizeof(float);
    cudaFuncSetAttribute(ep_kernel, cudaFuncAttributeMaxDynamicSharedMemorySize, (int)shmem);
    ep_kernel<<<blocks, TPB, shmem>>>(dr, ori, nor, W0, b0, W1, b1, W2, b2, f1, f2, out, B);
}

// round 13
// speedup vs baseline: 1.9607x; 1.1606x over previous
#include <cuda_runtime.h>
#include <cuda_fp16.h>
#include <math.h>

#define EPSF 1e-8f
#define NBC 64
#define NN 20
#define LPB 21
#define TPB (LPB*32)

// block weights (floats)
static constexpr int OW2=0, OB0=64, OB1=128, OMISC=192,
    OW0T=200,    // fp16 W0^T [j=64][24h] (k=i dim padded) = 768 fl
    OW0T4=968,   // fp16 W0 [i=16][72h] (k=hidden) = 576 fl
    OW1H=1544,   // fp16 W1 [k][j] stride 72h = 2304 fl
    OW1HT=3848,  // fp16 W1^T [j][k] stride 72h = 2304 fl
    WFL=6152;
// per-lane (floats)
static constexpr int LNDN=0, LNOR=60, LNEWR=240, LP=240, LFCR=260, LGO=260, LSO=280,
    LZ=292, LENC=LZ, LGZ=316, LGPRE=340, LSC=360,
    // region A (864 fl): DRW/RR/SEL -> featH fp16[24][24h] -> GA2 fp16[24][72h] -> GF fp32[20][16]
    LRA=368, LDRW=368, LRR=560, LSEL=624,
    // region B (864 fl): h1T fp16 [24][72h] -> ga1 fp16 (in-place)
    LRB=1232, LANE_F=2096;
static constexpr int SMEM_FLOATS = WFL + LPB*LANE_F;   // 50168 fl = 200672 B

typedef unsigned int u32;
__device__ __forceinline__ float ex2a(float x){ float r; asm("ex2.approx.f32 %0, %1;":"=f"(r):"f"(x)); return r; }
__device__ __forceinline__ float lg2a(float x){ float r; asm("lg2.approx.f32 %0, %1;":"=f"(r):"f"(x)); return r; }
__device__ __forceinline__ float rcpa(float x){ float r; asm("rcp.approx.f32 %0, %1;":"=f"(r):"f"(x)); return r; }
__device__ __forceinline__ float tanhfst(float x){
    float e = ex2a(x * 2.885390082f);
    return fmaf(-2.0f, rcpa(e + 1.0f), 1.0f);
}
__device__ __forceinline__ void hmma(float&d0,float&d1,float&d2,float&d3,
                                     u32 a0,u32 a1,u32 a2,u32 a3,u32 b0,u32 b1){
    asm volatile("mma.sync.aligned.m16n8k16.row.col.f32.f16.f16.f32 "
                 "{%0,%1,%2,%3},{%4,%5,%6,%7},{%8,%9},{%0,%1,%2,%3};"
                 : "+f"(d0),"+f"(d1),"+f"(d2),"+f"(d3)
                 : "r"(a0),"r"(a1),"r"(a2),"r"(a3),"r"(b0),"r"(b1));
}

__global__ __launch_bounds__(TPB, 1)
void ep_kernel(const float* __restrict__ dr, const float* __restrict__ orientation,
               const float* __restrict__ n_or,
               const float* __restrict__ W0, const float* __restrict__ b0,
               const float* __restrict__ W1, const float* __restrict__ b1,
               const float* __restrict__ W2, const float* __restrict__ b2,
               const float* __restrict__ f1, const float* __restrict__ f2,
               float* __restrict__ out, int B)
{
    extern __shared__ float sm[];
    const int tid = threadIdx.x;
    // zero fp16 weight tiles (padding must be 0)
    for (int idx=tid; idx<768; idx+=TPB) ((u32*)(sm+OW0T))[idx]=0u;
    for (int idx=tid; idx<576; idx+=TPB) ((u32*)(sm+OW0T4))[idx]=0u;
    __syncthreads();
    {
        __half* w0t  = (__half*)(sm+OW0T);
        __half* w0t4 = (__half*)(sm+OW0T4);
        for (int idx=tid; idx<960; idx+=TPB){
            int i=idx>>6, j=idx&63; __half hv=__float2half(W0[idx]);
            w0t[j*24+i]=hv; w0t4[i*72+j]=hv;
        }
        __half* w1h  = (__half*)(sm+OW1H);
        __half* w1ht = (__half*)(sm+OW1HT);
        for (int idx=tid; idx<4096; idx+=TPB){
            int k=idx>>6, j=idx&63; __half hv=__float2half(W1[idx]);
            w1h[k*72+j]=hv; w1ht[j*72+k]=hv;
        }
    }
    if (tid < 64) { sm[OW2+tid]=W2[tid]; sm[OB0+tid]=b0[tid]; sm[OB1+tid]=b1[tid]; }
    if (tid == 0) {
        sm[OMISC] = b2[0];
        #pragma unroll
        for (int j = 0; j < 3; j++) {
            float a=f1[j]; sm[OMISC+1+j]=a*a+EPSF;
            float p=f2[j]; sm[OMISC+4+j]=p*p+EPSF;
        }
    }
    __syncthreads();

    const u32* W1h32  = (const u32*)(sm+OW1H);
    const u32* W1hT32 = (const u32*)(sm+OW1HT);
    const u32* W0T32  = (const u32*)(sm+OW0T);
    const u32* WT4_32 = (const u32*)(sm+OW0T4);

    const int li = tid >> 5, t = tid & 31;
    const int g = t >> 2, tg = t & 3;         // MMA fragment mapping
    const int batch0 = blockIdx.x * LPB + li;
    const bool wr = batch0 < B;
    const int batch = wr ? batch0 : 0;
    float* L = sm + WFL + li * LANE_F;
    int* selp = (int*)(L + LSEL);
    __half* H1Th = (__half*)(L + LRB);
    u32*    H1T32 = (u32*)(L + LRB);
    __half* GA2h = (__half*)(L + LRA);
    const u32* GA2_32 = (const u32*)(L + LRA);

    // A: stage dr + orientation
    {
        const float4* src = (const float4*)(dr + (size_t)batch * 192);
        float4* dst = (float4*)(L + LDRW);
        dst[t] = src[t];
        if (t < 16) dst[t+32] = src[t+32];
        if (t < 9) L[LSO+t] = orientation[(size_t)batch*9 + t];
    }
    __syncwarp();
    // B: radii
    #pragma unroll
    for (int c = 0; c < 2; c++) {
        int u = 2*t+c;
        float x=L[LDRW+u*3]+EPSF, y=L[LDRW+u*3+1]+EPSF, z=L[LDRW+u*3+2]+EPSF;
        L[LRR+u] = sqrtf(x*x+y*y+z*z);
    }
    __syncwarp();
    // C: stable rank
    {
        float Ru[2]; int rk[2];
        #pragma unroll
        for (int c=0;c<2;c++){ Ru[c]=L[LRR+2*t+c]; rk[c]=0; }
        const float4* R4 = (const float4*)(L + LRR);
        #pragma unroll 4
        for (int v4=0; v4<16; v4++){
            float4 rv = R4[v4]; int v = 4*v4;
            #pragma unroll
            for (int c=0;c<2;c++){
                int u = 2*t+c;
                rk[c] += (rv.x<Ru[c])||(rv.x==Ru[c]&&v  <u);
                rk[c] += (rv.y<Ru[c])||(rv.y==Ru[c]&&v+1<u);
                rk[c] += (rv.z<Ru[c])||(rv.z==Ru[c]&&v+2<u);
                rk[c] += (rv.w<Ru[c])||(rv.w==Ru[c]&&v+3<u);
            }
        }
        #pragma unroll
        for (int c=0;c<2;c++) if (rk[c] < NN) selp[rk[c]] = 2*t+c;
    }
    __syncwarp();
    // D: gather top-20
    if (t < NN) {
        int u = selp[t];
        float Rv = L[LRR+u];
        L[LNEWR+t] = Rv;
        float inv = 1.0f / Rv;
        L[LNDN+t*3+0] = (L[LDRW+u*3+0]+EPSF)*inv;
        L[LNDN+t*3+1] = (L[LDRW+u*3+1]+EPSF)*inv;
        L[LNDN+t*3+2] = (L[LDRW+u*3+2]+EPSF)*inv;
        L[LFCR+t] = (Rv > 4.8f) ? 0.0f : (0.5f*cospif(Rv*(1.0f/4.8f)) + 0.5f);
        const float* np_ = n_or + ((size_t)batch*NBC + u)*9;
        #pragma unroll
        for (int e = 0; e < 9; e++) L[LNOR+t*9+e] = np_[e];
    }
    __syncwarp();
    // E: features -> fp16 featH [n][24h] (over dead DRW/RR/SEL); zero-pad first
    {
        u32* FZ = (u32*)(L+LRA);
        for (int idx=t; idx<288; idx+=32) FZ[idx]=0u;
    }
    __syncwarp();
    {
        __half* FH = (__half*)(L+LRA);
        int n = (t * 0x8889) >> 19;
        int i = t - n*15;
        #pragma unroll
        for (int it = 0; it < 10; it++) {
            int p = t + 32*it;
            if (p < 300) {
                const float* nd = L+LNDN+n*3; const float* NO = L+LNOR+n*9; const float* O = L+LSO;
                float v;
                if (i < 3)      v = nd[0]*O[i]   + nd[1]*O[3+i]   + nd[2]*O[6+i];
                else if (i < 6){ int h=i-3; v = nd[0]*NO[h] + nd[1]*NO[3+h] + nd[2]*NO[6+h]; }
                else { int l=(i-6)/3, m=(i-6)%3; v = O[l]*NO[m] + O[3+l]*NO[3+m] + O[6+l]*NO[6+m]; }
                FH[n*24+i] = __float2half(v);
            }
            n += 2; i += 2;
            if (i >= 15) { i -= 15; n += 1; }
        }
    }
    __syncwarp();

    // F: GEMM1 via mma: h1[j][n] = b0 + W0^T @ feat   (M=j, K=i(16), N=n)
    {
        const u32* FH32 = (const u32*)(L+LRA);
        float b0g[4], b0g8[4];
        #pragma unroll
        for (int mt=0; mt<4; mt++){ b0g[mt]=sm[OB0+mt*16+g]; b0g8[mt]=sm[OB0+mt*16+g+8]; }
        float h[3][4][4];
        #pragma unroll
        for (int nt=0; nt<3; nt++)
            #pragma unroll
            for (int mt=0; mt<4; mt++){
                h[nt][mt][0]=b0g[mt]; h[nt][mt][1]=b0g[mt];
                h[nt][mt][2]=b0g8[mt]; h[nt][mt][3]=b0g8[mt];
            }
        u32 A0[4],A1[4],A2[4],A3[4];
        #pragma unroll
        for (int mt=0; mt<4; mt++){
            int ba=(mt*16+g)*12+tg;
            A0[mt]=W0T32[ba]; A1[mt]=W0T32[ba+96]; A2[mt]=W0T32[ba+4]; A3[mt]=W0T32[ba+100];
        }
        #pragma unroll
        for (int nt=0; nt<3; nt++){
            int bb=(nt*8+g)*12+tg;
            u32 bf0=FH32[bb], bf1=FH32[bb+4];
            #pragma unroll
            for (int mt=0; mt<4; mt++)
                hmma(h[nt][mt][0],h[nt][mt][1],h[nt][mt][2],h[nt][mt][3],
                     A0[mt],A1[mt],A2[mt],A3[mt],bf0,bf1);
        }
        #pragma unroll
        for (int nt=0; nt<3; nt++)
            #pragma unroll
            for (int mt=0; mt<4; mt++){
                int n0=nt*8+2*tg, j0=mt*16+g;
                H1Th[ n0   *72 + j0  ] = __float2half(tanhfst(h[nt][mt][0]));
                H1Th[(n0+1)*72 + j0  ] = __float2half(tanhfst(h[nt][mt][1]));
                H1Th[ n0   *72 + j0+8] = __float2half(tanhfst(h[nt][mt][2]));
                H1Th[(n0+1)*72 + j0+8] = __float2half(tanhfst(h[nt][mt][3]));
            }
    }
    __syncwarp();

    // Bias/w2 fragment scalars
    float b1g[4], b1g8[4], w2g[4], w2g8[4];
    #pragma unroll
    for (int mt=0; mt<4; mt++){
        b1g[mt]  = sm[OB1 + mt*16 + g];
        b1g8[mt] = sm[OB1 + mt*16 + g + 8];
        w2g[mt]  = sm[OW2 + mt*16 + g];
        w2g8[mt] = sm[OW2 + mt*16 + g + 8];
    }

    // G: GEMM2 via mma: h2 = b1 + W1^T @ h1   (M=j, K=k, N=n)
    float d[3][4][4];
    #pragma unroll
    for (int nt=0; nt<3; nt++)
        #pragma unroll
        for (int mt=0; mt<4; mt++){
            d[nt][mt][0]=b1g[mt]; d[nt][mt][1]=b1g[mt];
            d[nt][mt][2]=b1g8[mt]; d[nt][mt][3]=b1g8[mt];
        }
    #pragma unroll
    for (int kt=0; kt<4; kt++){
        u32 A0[4],A1[4],A2[4],A3[4];
        #pragma unroll
        for (int mt=0; mt<4; mt++){
            int base = (mt*16+g)*36 + kt*8 + tg;
            A0[mt]=W1hT32[base];   A1[mt]=W1hT32[base+288];
            A2[mt]=W1hT32[base+4]; A3[mt]=W1hT32[base+292];
        }
        #pragma unroll
        for (int nt=0; nt<3; nt++){
            int bb = (nt*8+g)*36 + kt*8 + tg;
            u32 bf0 = H1T32[bb], bf1 = H1T32[bb+4];
            #pragma unroll
            for (int mt=0; mt<4; mt++)
                hmma(d[nt][mt][0],d[nt][mt][1],d[nt][mt][2],d[nt][mt][3],
                     A0[mt],A1[mt],A2[mt],A3[mt],bf0,bf1);
        }
    }
    #pragma unroll
    for (int nt=0; nt<3; nt++)
        #pragma unroll
        for (int mt=0; mt<4; mt++)
            #pragma unroll
            for (int c=0;c<4;c++) d[nt][mt][c] = tanhfst(d[nt][mt][c]);

    // H1: z[n] via fragment butterfly
    {
        float zp0[3], zp1[3];
        #pragma unroll
        for (int nt=0; nt<3; nt++){
            float p0=0.f, p1=0.f;
            #pragma unroll
            for (int mt=0; mt<4; mt++){
                p0 += w2g[mt]*d[nt][mt][0] + w2g8[mt]*d[nt][mt][2];
                p1 += w2g[mt]*d[nt][mt][1] + w2g8[mt]*d[nt][mt][3];
            }
            zp0[nt]=p0; zp1[nt]=p1;
        }
        #pragma unroll
        for (int m=4;m<32;m<<=1){
            #pragma unroll
            for (int nt=0; nt<3; nt++){
                zp0[nt] += __shfl_xor_sync(0xffffffffu, zp0[nt], m);
                zp1[nt] += __shfl_xor_sync(0xffffffffu, zp1[nt], m);
            }
        }
        if (g==0){
            float b2v = sm[OMISC];
            #pragma unroll
            for (int nt=0; nt<3; nt++){
                float2 v; v.x = zp0[nt]+b2v; v.y = zp1[nt]+b2v;
                *(float2*)(L + LZ + nt*8 + 2*tg) = v;
            }
        }
    }
    __syncwarp();
    // H2: enc, prior per n
    if (t < NN){
        float enc = tanhfst(L[LZ+t]);
        float e = enc*enc + EPSF;
        float Rm = L[LNEWR+t] - e;
        float P=0.f, D=0.f;
        #pragma unroll
        for (int j=0;j<3;j++){
            float a=sm[OMISC+1+j], p=sm[OMISC+4+j];
            float tt = ex2a(-p * lg2a(a*Rm));
            P += tt; D += p*tt;
        }
        L[LP+t]=P; L[LGPRE+t]=D/Rm; L[LENC+t]=enc;
    }
    __syncwarp();
    if (t==0){
        float S=0.f, F=0.f;
        #pragma unroll
        for (int n=0;n<NN;n++){ S+=L[LP+n]; F+=L[LFCR+n]; }
        L[LSC]=S; L[LSC+1]=F;
    }
    __syncwarp();
    if (t < NN){
        float enc=L[LENC+t];
        L[LGZ+t] = L[LSC+1]*L[LGPRE+t]*2.f*enc*(1.f-enc*enc);
        if (wr) out[(size_t)6*B + (size_t)batch*NN + t] = L[LSC]*L[LFCR+t];
    } else if (t < 24) {
        L[LGZ+t] = 0.f;
    }
    __syncwarp();
    // I: ga2 -> fp16 [n][j] stride 72 (region A, over dead featH)
    #pragma unroll
    for (int nt=0; nt<3; nt++){
        float2 gz2 = *(const float2*)(L + LGZ + nt*8 + 2*tg);
        int n0 = nt*8 + 2*tg;
        #pragma unroll
        for (int mt=0; mt<4; mt++){
            int j0 = mt*16 + g;
            float v00 = gz2.x * w2g[mt]  * (1.f - d[nt][mt][0]*d[nt][mt][0]);
            float v01 = gz2.y * w2g[mt]  * (1.f - d[nt][mt][1]*d[nt][mt][1]);
            float v02 = gz2.x * w2g8[mt] * (1.f - d[nt][mt][2]*d[nt][mt][2]);
            float v03 = gz2.y * w2g8[mt] * (1.f - d[nt][mt][3]*d[nt][mt][3]);
            GA2h[ n0   *72 + j0  ] = __float2half(v00);
            GA2h[(n0+1)*72 + j0  ] = __float2half(v01);
            GA2h[ n0   *72 + j0+8] = __float2half(v02);
            GA2h[(n0+1)*72 + j0+8] = __float2half(v03);
        }
    }
    __syncwarp();
    // J: GEMM3 via mma: gh1[k][n] = W1 @ ga2   (M=k, K=j, N=n)
    float e3[3][4][4];
    #pragma unroll
    for (int nt=0; nt<3; nt++)
        #pragma unroll
        for (int mt=0; mt<4; mt++)
            #pragma unroll
            for (int c=0;c<4;c++) e3[nt][mt][c]=0.f;
    #pragma unroll
    for (int kt=0; kt<4; kt++){
        u32 A0[4],A1[4],A2[4],A3[4];
        #pragma unroll
        for (int mt=0; mt<4; mt++){
            int base = (mt*16+g)*36 + kt*8 + tg;
            A0[mt]=W1h32[base];   A1[mt]=W1h32[base+288];
            A2[mt]=W1h32[base+4]; A3[mt]=W1h32[base+292];
        }
        #pragma unroll
        for (int nt=0; nt<3; nt++){
            int bb = (nt*8+g)*36 + kt*8 + tg;
            u32 bf0 = GA2_32[bb], bf1 = GA2_32[bb+4];
            #pragma unroll
            for (int mt=0; mt<4; mt++)
                hmma(e3[nt][mt][0],e3[nt][mt][1],e3[nt][mt][2],e3[nt][mt][3],
                     A0[mt],A1[mt],A2[mt],A3[mt],bf0,bf1);
        }
    }
    // ga1 = gh1*(1-h1^2) fp16, IN-PLACE over h1T (same thread, same address)
    #pragma unroll
    for (int nt=0; nt<3; nt++){
        int n0 = nt*8 + 2*tg;
        if (n0 < 20){
            #pragma unroll
            for (int mt=0; mt<4; mt++){
                int k = mt*16 + g;
                int ix = n0*72 + k;
                float hv = __half2float(H1Th[ix]);
                H1Th[ix] = __float2half(e3[nt][mt][0]*(1.f-hv*hv));
                ix = (n0+1)*72 + k;
                hv = __half2float(H1Th[ix]);
                H1Th[ix] = __float2half(e3[nt][mt][1]*(1.f-hv*hv));
                ix = n0*72 + k + 8;
                hv = __half2float(H1Th[ix]);
                H1Th[ix] = __float2half(e3[nt][mt][2]*(1.f-hv*hv));
                ix = (n0+1)*72 + k + 8;
                hv = __half2float(H1Th[ix]);
                H1Th[ix] = __float2half(e3[nt][mt][3]*(1.f-hv*hv));
            }
        }
    }
    __syncwarp();
    // K: GEMM4 via mma: gfeat[n][i] = ga1^T @ W0^T  (M=n: tiles at base 0 and 8; N=i(16); K=64)
    {
        const u32* GA1_32 = (const u32*)(L+LRB);
        float gf[2][2][4];
        #pragma unroll
        for (int nt=0; nt<2; nt++)
            #pragma unroll
            for (int mt=0; mt<2; mt++)
                #pragma unroll
                for (int c=0;c<4;c++) gf[nt][mt][c]=0.f;
        #pragma unroll
        for (int kt=0; kt<4; kt++){
            u32 A0[2],A1[2],A2[2],A3[2];
            #pragma unroll
            for (int mt=0; mt<2; mt++){
                int ba = (mt*8+g)*36 + kt*8 + tg;
                A0[mt]=GA1_32[ba];   A1[mt]=GA1_32[ba+288];
                A2[mt]=GA1_32[ba+4]; A3[mt]=GA1_32[ba+292];
            }
            #pragma unroll
            for (int nt=0; nt<2; nt++){
                int bb = (nt*8+g)*36 + kt*8 + tg;
                u32 bf0 = WT4_32[bb], bf1 = WT4_32[bb+4];
                #pragma unroll
                for (int mt=0; mt<2; mt++)
                    hmma(gf[nt][mt][0],gf[nt][mt][1],gf[nt][mt][2],gf[nt][mt][3],
                         A0[mt],A1[mt],A2[mt],A3[mt],bf0,bf1);
            }
        }
        float* GF = L + LRA;   // over dead GA2
        #pragma unroll
        for (int nt=0; nt<2; nt++){
            int i0 = nt*8 + 2*tg;
            GF[ g    *16 + i0  ] = gf[nt][0][0];
            GF[ g    *16 + i0+1] = gf[nt][0][1];
            GF[(g+8) *16 + i0  ] = gf[nt][0][2];
            GF[(g+8) *16 + i0+1] = gf[nt][0][3];
            if (g < 4){
                GF[(16+g)*16 + i0  ] = gf[nt][1][2];
                GF[(16+g)*16 + i0+1] = gf[nt][1][3];
            }
        }
    }
    __syncwarp();
    // L: force, gO (front LGO), torque
    if (t < 3){
        float f=0.f; const float* O=L+LSO;
        for (int n=0;n<NN;n++){
            const float* gg=L+LRA+n*16; const float* NO=L+LNOR+n*9;
            f += gg[0]*O[t*3]+gg[1]*O[t*3+1]+gg[2]*O[t*3+2];
            f += gg[3]*NO[t*3]+gg[4]*NO[t*3+1]+gg[5]*NO[t*3+2];
        }
        if (wr) out[(size_t)batch*3+t]=f;
    }
    if (t >= 4 && t < 13){
        int a=(t-4)/3, bb=(t-4)%3; float g2=0.f;
        for (int n=0;n<NN;n++){
            const float* gg=L+LRA+n*16; const float* NO=L+LNOR+n*9;
            g2 += L[LNDN+n*3+a]*gg[bb];
            g2 += gg[6+3*bb+0]*NO[a*3+0]+gg[6+3*bb+1]*NO[a*3+1]+gg[6+3*bb+2]*NO[a*3+2];
        }
        L[LGO+a*3+bb]=g2;
    }
    __syncwarp();
    if (t==0 && wr){
        const float* gO=L+LGO; const float* O=L+LSO;
        float tx=0.f,ty=0.f,tz=0.f;
        #pragma unroll
        for (int c=0;c<3;c++){
            float u0=gO[c],u1=gO[3+c],u2=gO[6+c];
            float v0=O[c], v1=O[3+c], v2=O[6+c];
            tx += u1*v2-u2*v1; ty += u2*v0-u0*v2; tz += u0*v1-u1*v0;
        }
        out[(size_t)3*B+(size_t)batch*3+0]=tx;
        out[(size_t)3*B+(size_t)batch*3+1]=ty;
        out[(size_t)3*B+(size_t)batch*3+2]=tz;
    }
}

extern "C" void kernel_launch(void* const* d_in, const int* in_sizes, int n_in,
                              void* d_out, int out_size) {
    const float* dr  = (const float*)d_in[0];
    const float* ori = (const float*)d_in[1];
    const float* nor = (const float*)d_in[2];
    const float* W0  = (const float*)d_in[3];
    const float* b0  = (const float*)d_in[4];
    const float* W1  = (const float*)d_in[5];
    const float* b1  = (const float*)d_in[6];
    const float* W2  = (const float*)d_in[7];
    const float* b2  = (const float*)d_in[8];
    const float* f1  = (const float*)d_in[9];
    const float* f2  = (const float*)d_in[10];
    float* out = (float*)d_out;

    int B = in_sizes[0] / (NBC * 3);
    int blocks = (B + LPB - 1) / LPB;
    size_t shmem = (size_t)SMEM_FLOATS * sizeof(float);
    cudaFuncSetAttribute(ep_kernel, cudaFuncAttributeMaxDynamicSharedMemorySize, (int)shmem);
    ep_kernel<<<blocks, TPB, shmem>>>(dr, ori, nor, W0, b0, W1, b1, W2, b2, f1, f2, out, B);
}

// round 14
// speedup vs baseline: 2.2243x; 1.1344x over previous
#include <cuda_runtime.h>
#include <cuda_fp16.h>
#include <math.h>

#define EPSF 1e-8f
#define NBC 64
#define NN 20
#define LPB 24
#define TPB (LPB*32)

// block weights (floats)
static constexpr int OW2=0, OB0=64, OB1=128, OMISC=192,
    OW0T=200,    // fp16 W0^T [j=64][24h] = 768 fl
    OW0T4=968,   // fp16 W0 [i=16][72h] = 576 fl
    OW1H=1544,   // fp16 W1 [k][j] stride 72h = 2304 fl
    OW1HT=3848,  // fp16 W1^T [j][k] stride 72h = 2304 fl
    WFL=6152;
// per-lane (floats)
static constexpr int LNDN=0, LNOR=60, LNEWR=240, LP=240, LFCR=260, LGO=260, LSO=280,
    LZ=292, LENC=LZ, LGZ=316, LGPRE=340, LSC=360,
    LRA=368, LDRW=368, LRR=560, LSEL=624,    // region A: DRW/RR/SEL -> featH -> GA2 -> GF
    LRB=1232, LANE_F=2096;                    // region B: h1T fp16 -> ga1 fp16 in-place
static constexpr int SMEM_FLOATS = WFL + LPB*LANE_F;   // 56456 fl = 225824 B

typedef unsigned int u32;
__device__ __forceinline__ float ex2a(float x){ float r; asm("ex2.approx.f32 %0, %1;":"=f"(r):"f"(x)); return r; }
__device__ __forceinline__ float lg2a(float x){ float r; asm("lg2.approx.f32 %0, %1;":"=f"(r):"f"(x)); return r; }
__device__ __forceinline__ float rcpa(float x){ float r; asm("rcp.approx.f32 %0, %1;":"=f"(r):"f"(x)); return r; }
__device__ __forceinline__ float tanhfst(float x){
    float e = ex2a(x * 2.885390082f);
    return fmaf(-2.0f, rcpa(e + 1.0f), 1.0f);
}
__device__ __forceinline__ void hmma(float&d0,float&d1,float&d2,float&d3,
                                     u32 a0,u32 a1,u32 a2,u32 a3,u32 b0,u32 b1){
    asm volatile("mma.sync.aligned.m16n8k16.row.col.f32.f16.f16.f32 "
                 "{%0,%1,%2,%3},{%4,%5,%6,%7},{%8,%9},{%0,%1,%2,%3};"
                 : "+f"(d0),"+f"(d1),"+f"(d2),"+f"(d3)
                 : "r"(a0),"r"(a1),"r"(a2),"r"(a3),"r"(b0),"r"(b1));
}

__global__ __launch_bounds__(TPB, 1)
void ep_kernel(const float* __restrict__ dr, const float* __restrict__ orientation,
               const float* __restrict__ n_or,
               const float* __restrict__ W0, const float* __restrict__ b0,
               const float* __restrict__ W1, const float* __restrict__ b1,
               const float* __restrict__ W2, const float* __restrict__ b2,
               const float* __restrict__ f1, const float* __restrict__ f2,
               float* __restrict__ out, int B)
{
    extern __shared__ float sm[];
    const int tid = threadIdx.x;
    for (int idx=tid; idx<768; idx+=TPB) ((u32*)(sm+OW0T))[idx]=0u;
    for (int idx=tid; idx<576; idx+=TPB) ((u32*)(sm+OW0T4))[idx]=0u;
    __syncthreads();
    {
        __half* w0t  = (__half*)(sm+OW0T);
        __half* w0t4 = (__half*)(sm+OW0T4);
        for (int idx=tid; idx<960; idx+=TPB){
            int i=idx>>6, j=idx&63; __half hv=__float2half(W0[idx]);
            w0t[j*24+i]=hv; w0t4[i*72+j]=hv;
        }
        __half* w1h  = (__half*)(sm+OW1H);
        __half* w1ht = (__half*)(sm+OW1HT);
        for (int idx=tid; idx<4096; idx+=TPB){
            int k=idx>>6, j=idx&63; __half hv=__float2half(W1[idx]);
            w1h[k*72+j]=hv; w1ht[j*72+k]=hv;
        }
    }
    if (tid < 64) { sm[OW2+tid]=W2[tid]; sm[OB0+tid]=b0[tid]; sm[OB1+tid]=b1[tid]; }
    if (tid == 0) {
        sm[OMISC] = b2[0];
        #pragma unroll
        for (int j = 0; j < 3; j++) {
            float a=f1[j]; sm[OMISC+1+j]=a*a+EPSF;
            float p=f2[j]; sm[OMISC+4+j]=p*p+EPSF;
        }
    }
    __syncthreads();

    const u32* W1h32  = (const u32*)(sm+OW1H);
    const u32* W1hT32 = (const u32*)(sm+OW1HT);
    const u32* W0T32  = (const u32*)(sm+OW0T);
    const u32* WT4_32 = (const u32*)(sm+OW0T4);

    const int li = tid >> 5, t = tid & 31;
    const int g = t >> 2, tg = t & 3;
    const int batch0 = blockIdx.x * LPB + li;
    const bool wr = batch0 < B;
    const int batch = wr ? batch0 : 0;
    float* L = sm + WFL + li * LANE_F;
    int* selp = (int*)(L + LSEL);
    __half* H1Th = (__half*)(L + LRB);
    u32*    H1T32 = (u32*)(L + LRB);
    __half* GA2h = (__half*)(L + LRA);
    const u32* GA2_32 = (const u32*)(L + LRA);

    // A: stage dr + orientation
    {
        const float4* src = (const float4*)(dr + (size_t)batch * 192);
        float4* dst = (float4*)(L + LDRW);
        dst[t] = src[t];
        if (t < 16) dst[t+32] = src[t+32];
        if (t < 9) L[LSO+t] = orientation[(size_t)batch*9 + t];
    }
    __syncwarp();
    // B: radii
    #pragma unroll
    for (int c = 0; c < 2; c++) {
        int u = 2*t+c;
        float x=L[LDRW+u*3]+EPSF, y=L[LDRW+u*3+1]+EPSF, z=L[LDRW+u*3+2]+EPSF;
        L[LRR+u] = sqrtf(x*x+y*y+z*z);
    }
    __syncwarp();
    // C: stable rank
    {
        float Ru[2]; int rk[2];
        #pragma unroll
        for (int c=0;c<2;c++){ Ru[c]=L[LRR+2*t+c]; rk[c]=0; }
        const float4* R4 = (const float4*)(L + LRR);
        #pragma unroll 4
        for (int v4=0; v4<16; v4++){
            float4 rv = R4[v4]; int v = 4*v4;
            #pragma unroll
            for (int c=0;c<2;c++){
                int u = 2*t+c;
                rk[c] += (rv.x<Ru[c])||(rv.x==Ru[c]&&v  <u);
                rk[c] += (rv.y<Ru[c])||(rv.y==Ru[c]&&v+1<u);
                rk[c] += (rv.z<Ru[c])||(rv.z==Ru[c]&&v+2<u);
                rk[c] += (rv.w<Ru[c])||(rv.w==Ru[c]&&v+3<u);
            }
        }
        #pragma unroll
        for (int c=0;c<2;c++) if (rk[c] < NN) selp[rk[c]] = 2*t+c;
    }
    __syncwarp();
    // D: gather top-20
    if (t < NN) {
        int u = selp[t];
        float Rv = L[LRR+u];
        L[LNEWR+t] = Rv;
        float inv = 1.0f / Rv;
        L[LNDN+t*3+0] = (L[LDRW+u*3+0]+EPSF)*inv;
        L[LNDN+t*3+1] = (L[LDRW+u*3+1]+EPSF)*inv;
        L[LNDN+t*3+2] = (L[LDRW+u*3+2]+EPSF)*inv;
        L[LFCR+t] = (Rv > 4.8f) ? 0.0f : (0.5f*cospif(Rv*(1.0f/4.8f)) + 0.5f);
        const float* np_ = n_or + ((size_t)batch*NBC + u)*9;
        #pragma unroll
        for (int e = 0; e < 9; e++) L[LNOR+t*9+e] = np_[e];
    }
    __syncwarp();
    // E: features -> fp16 featH [n][24h] (over dead DRW/RR/SEL); zero-pad first
    {
        u32* FZ = (u32*)(L+LRA);
        for (int idx=t; idx<288; idx+=32) FZ[idx]=0u;
    }
    __syncwarp();
    {
        __half* FH = (__half*)(L+LRA);
        int n = (t * 0x8889) >> 19;
        int i = t - n*15;
        #pragma unroll
        for (int it = 0; it < 10; it++) {
            int p = t + 32*it;
            if (p < 300) {
                const float* nd = L+LNDN+n*3; const float* NO = L+LNOR+n*9; const float* O = L+LSO;
                float v;
                if (i < 3)      v = nd[0]*O[i]   + nd[1]*O[3+i]   + nd[2]*O[6+i];
                else if (i < 6){ int h=i-3; v = nd[0]*NO[h] + nd[1]*NO[3+h] + nd[2]*NO[6+h]; }
                else { int l=(i-6)/3, m=(i-6)%3; v = O[l]*NO[m] + O[3+l]*NO[3+m] + O[6+l]*NO[6+m]; }
                FH[n*24+i] = __float2half(v);
            }
            n += 2; i += 2;
            if (i >= 15) { i -= 15; n += 1; }
        }
    }
    __syncwarp();

    // F: GEMM1 via mma: h1[j][n] = b0 + W0^T @ feat
    {
        const u32* FH32 = (const u32*)(L+LRA);
        float b0g[4], b0g8[4];
        #pragma unroll
        for (int mt=0; mt<4; mt++){ b0g[mt]=sm[OB0+mt*16+g]; b0g8[mt]=sm[OB0+mt*16+g+8]; }
        float h[3][4][4];
        #pragma unroll
        for (int nt=0; nt<3; nt++)
            #pragma unroll
            for (int mt=0; mt<4; mt++){
                h[nt][mt][0]=b0g[mt]; h[nt][mt][1]=b0g[mt];
                h[nt][mt][2]=b0g8[mt]; h[nt][mt][3]=b0g8[mt];
            }
        u32 A0[4],A1[4],A2[4],A3[4];
        #pragma unroll
        for (int mt=0; mt<4; mt++){
            int ba=(mt*16+g)*12+tg;
            A0[mt]=W0T32[ba]; A1[mt]=W0T32[ba+96]; A2[mt]=W0T32[ba+4]; A3[mt]=W0T32[ba+100];
        }
        #pragma unroll
        for (int nt=0; nt<3; nt++){
            int bb=(nt*8+g)*12+tg;
            u32 bf0=FH32[bb], bf1=FH32[bb+4];
            #pragma unroll
            for (int mt=0; mt<4; mt++)
                hmma(h[nt][mt][0],h[nt][mt][1],h[nt][mt][2],h[nt][mt][3],
                     A0[mt],A1[mt],A2[mt],A3[mt],bf0,bf1);
        }
        #pragma unroll
        for (int nt=0; nt<3; nt++)
            #pragma unroll
            for (int mt=0; mt<4; mt++){
                int n0=nt*8+2*tg, j0=mt*16+g;
                H1Th[ n0   *72 + j0  ] = __float2half(tanhfst(h[nt][mt][0]));
                H1Th[(n0+1)*72 + j0  ] = __float2half(tanhfst(h[nt][mt][1]));
                H1Th[ n0   *72 + j0+8] = __float2half(tanhfst(h[nt][mt][2]));
                H1Th[(n0+1)*72 + j0+8] = __float2half(tanhfst(h[nt][mt][3]));
            }
    }
    __syncwarp();

    float b1g[4], b1g8[4], w2g[4], w2g8[4];
    #pragma unroll
    for (int mt=0; mt<4; mt++){
        b1g[mt]  = sm[OB1 + mt*16 + g];
        b1g8[mt] = sm[OB1 + mt*16 + g + 8];
        w2g[mt]  = sm[OW2 + mt*16 + g];
        w2g8[mt] = sm[OW2 + mt*16 + g + 8];
    }

    // G: GEMM2 via mma: h2 = b1 + W1^T @ h1
    float d[3][4][4];
    #pragma unroll
    for (int nt=0; nt<3; nt++)
        #pragma unroll
        for (int mt=0; mt<4; mt++){
            d[nt][mt][0]=b1g[mt]; d[nt][mt][1]=b1g[mt];
            d[nt][mt][2]=b1g8[mt]; d[nt][mt][3]=b1g8[mt];
        }
    #pragma unroll
    for (int kt=0; kt<4; kt++){
        u32 A0[4],A1[4],A2[4],A3[4];
        #pragma unroll
        for (int mt=0; mt<4; mt++){
            int base = (mt*16+g)*36 + kt*8 + tg;
            A0[mt]=W1hT32[base];   A1[mt]=W1hT32[base+288];
            A2[mt]=W1hT32[base+4]; A3[mt]=W1hT32[base+292];
        }
        #pragma unroll
        for (int nt=0; nt<3; nt++){
            int bb = (nt*8+g)*36 + kt*8 + tg;
            u32 bf0 = H1T32[bb], bf1 = H1T32[bb+4];
            #pragma unroll
            for (int mt=0; mt<4; mt++)
                hmma(d[nt][mt][0],d[nt][mt][1],d[nt][mt][2],d[nt][mt][3],
                     A0[mt],A1[mt],A2[mt],A3[mt],bf0,bf1);
        }
    }
    #pragma unroll
    for (int nt=0; nt<3; nt++)
        #pragma unroll
        for (int mt=0; mt<4; mt++)
            #pragma unroll
            for (int c=0;c<4;c++) d[nt][mt][c] = tanhfst(d[nt][mt][c]);

    // H1: z[n] via fragment butterfly
    {
        float zp0[3], zp1[3];
        #pragma unroll
        for (int nt=0; nt<3; nt++){
            float p0=0.f, p1=0.f;
            #pragma unroll
            for (int mt=0; mt<4; mt++){
                p0 += w2g[mt]*d[nt][mt][0] + w2g8[mt]*d[nt][mt][2];
                p1 += w2g[mt]*d[nt][mt][1] + w2g8[mt]*d[nt][mt][3];
            }
            zp0[nt]=p0; zp1[nt]=p1;
        }
        #pragma unroll
        for (int m=4;m<32;m<<=1){
            #pragma unroll
            for (int nt=0; nt<3; nt++){
                zp0[nt] += __shfl_xor_sync(0xffffffffu, zp0[nt], m);
                zp1[nt] += __shfl_xor_sync(0xffffffffu, zp1[nt], m);
            }
        }
        if (g==0){
            float b2v = sm[OMISC];
            #pragma unroll
            for (int nt=0; nt<3; nt++){
                float2 v; v.x = zp0[nt]+b2v; v.y = zp1[nt]+b2v;
                *(float2*)(L + LZ + nt*8 + 2*tg) = v;
            }
        }
    }
    __syncwarp();
    // H2: enc, prior per n
    if (t < NN){
        float enc = tanhfst(L[LZ+t]);
        float e = enc*enc + EPSF;
        float Rm = L[LNEWR+t] - e;
        float P=0.f, D=0.f;
        #pragma unroll
        for (int j=0;j<3;j++){
            float a=sm[OMISC+1+j], p=sm[OMISC+4+j];
            float tt = ex2a(-p * lg2a(a*Rm));
            P += tt; D += p*tt;
        }
        L[LP+t]=P; L[LGPRE+t]=D/Rm; L[LENC+t]=enc;
    }
    __syncwarp();
    if (t==0){
        float S=0.f, F=0.f;
        #pragma unroll
        for (int n=0;n<NN;n++){ S+=L[LP+n]; F+=L[LFCR+n]; }
        L[LSC]=S; L[LSC+1]=F;
    }
    __syncwarp();
    if (t < NN){
        float enc=L[LENC+t];
        L[LGZ+t] = L[LSC+1]*L[LGPRE+t]*2.f*enc*(1.f-enc*enc);
        if (wr) out[(size_t)6*B + (size_t)batch*NN + t] = L[LSC]*L[LFCR+t];
    } else if (t < 24) {
        L[LGZ+t] = 0.f;
    }
    __syncwarp();
    // I: ga2 -> fp16 [n][j] stride 72
    #pragma unroll
    for (int nt=0; nt<3; nt++){
        float2 gz2 = *(const float2*)(L + LGZ + nt*8 + 2*tg);
        int n0 = nt*8 + 2*tg;
        #pragma unroll
        for (int mt=0; mt<4; mt++){
            int j0 = mt*16 + g;
            float v00 = gz2.x * w2g[mt]  * (1.f - d[nt][mt][0]*d[nt][mt][0]);
            float v01 = gz2.y * w2g[mt]  * (1.f - d[nt][mt][1]*d[nt][mt][1]);
            float v02 = gz2.x * w2g8[mt] * (1.f - d[nt][mt][2]*d[nt][mt][2]);
            float v03 = gz2.y * w2g8[mt] * (1.f - d[nt][mt][3]*d[nt][mt][3]);
            GA2h[ n0   *72 + j0  ] = __float2half(v00);
            GA2h[(n0+1)*72 + j0  ] = __float2half(v01);
            GA2h[ n0   *72 + j0+8] = __float2half(v02);
            GA2h[(n0+1)*72 + j0+8] = __float2half(v03);
        }
    }
    __syncwarp();
    // J: GEMM3 via mma: gh1[k][n] = W1 @ ga2
    float e3[3][4][4];
    #pragma unroll
    for (int nt=0; nt<3; nt++)
        #pragma unroll
        for (int mt=0; mt<4; mt++)
            #pragma unroll
            for (int c=0;c<4;c++) e3[nt][mt][c]=0.f;
    #pragma unroll
    for (int kt=0; kt<4; kt++){
        u32 A0[4],A1[4],A2[4],A3[4];
        #pragma unroll
        for (int mt=0; mt<4; mt++){
            int base = (mt*16+g)*36 + kt*8 + tg;
            A0[mt]=W1h32[base];   A1[mt]=W1h32[base+288];
            A2[mt]=W1h32[base+4]; A3[mt]=W1h32[base+292];
        }
        #pragma unroll
        for (int nt=0; nt<3; nt++){
            int bb = (nt*8+g)*36 + kt*8 + tg;
            u32 bf0 = GA2_32[bb], bf1 = GA2_32[bb+4];
            #pragma unroll
            for (int mt=0; mt<4; mt++)
                hmma(e3[nt][mt][0],e3[nt][mt][1],e3[nt][mt][2],e3[nt][mt][3],
                     A0[mt],A1[mt],A2[mt],A3[mt],bf0,bf1);
        }
    }
    // ga1 = gh1*(1-h1^2) fp16, IN-PLACE over h1T
    #pragma unroll
    for (int nt=0; nt<3; nt++){
        int n0 = nt*8 + 2*tg;
        if (n0 < 20){
            #pragma unroll
            for (int mt=0; mt<4; mt++){
                int k = mt*16 + g;
                int ix = n0*72 + k;
                float hv = __half2float(H1Th[ix]);
                H1Th[ix] = __float2half(e3[nt][mt][0]*(1.f-hv*hv));
                ix = (n0+1)*72 + k;
                hv = __half2float(H1Th[ix]);
                H1Th[ix] = __float2half(e3[nt][mt][1]*(1.f-hv*hv));
                ix = n0*72 + k + 8;
                hv = __half2float(H1Th[ix]);
                H1Th[ix] = __float2half(e3[nt][mt][2]*(1.f-hv*hv));
                ix = (n0+1)*72 + k + 8;
                hv = __half2float(H1Th[ix]);
                H1Th[ix] = __float2half(e3[nt][mt][3]*(1.f-hv*hv));
            }
        }
    }
    __syncwarp();
    // K: GEMM4 via mma: gfeat[n][i] = ga1^T @ W0^T
    {
        const u32* GA1_32 = (const u32*)(L+LRB);
        float gf[2][2][4];
        #pragma unroll
        for (int nt=0; nt<2; nt++)
            #pragma unroll
            for (int mt=0; mt<2; mt++)
                #pragma unroll
                for (int c=0;c<4;c++) gf[nt][mt][c]=0.f;
        #pragma unroll
        for (int kt=0; kt<4; kt++){
            u32 A0[2],A1[2],A2[2],A3[2];
            #pragma unroll
            for (int mt=0; mt<2; mt++){
                int ba = (mt*8+g)*36 + kt*8 + tg;
                A0[mt]=GA1_32[ba];   A1[mt]=GA1_32[ba+288];
                A2[mt]=GA1_32[ba+4]; A3[mt]=GA1_32[ba+292];
            }
            #pragma unroll
            for (int nt=0; nt<2; nt++){
                int bb = (nt*8+g)*36 + kt*8 + tg;
                u32 bf0 = WT4_32[bb], bf1 = WT4_32[bb+4];
                #pragma unroll
                for (int mt=0; mt<2; mt++)
                    hmma(gf[nt][mt][0],gf[nt][mt][1],gf[nt][mt][2],gf[nt][mt][3],
                         A0[mt],A1[mt],A2[mt],A3[mt],bf0,bf1);
            }
        }
        float* GF = L + LRA;
        #pragma unroll
        for (int nt=0; nt<2; nt++){
            int i0 = nt*8 + 2*tg;
            GF[ g    *16 + i0  ] = gf[nt][0][0];
            GF[ g    *16 + i0+1] = gf[nt][0][1];
            GF[(g+8) *16 + i0  ] = gf[nt][0][2];
            GF[(g+8) *16 + i0+1] = gf[nt][0][3];
            if (g < 4){
                GF[(16+g)*16 + i0  ] = gf[nt][1][2];
                GF[(16+g)*16 + i0+1] = gf[nt][1][3];
            }
        }
    }
    __syncwarp();
    // L: force, gO, torque
    if (t < 3){
        float f=0.f; const float* O=L+LSO;
        for (int n=0;n<NN;n++){
            const float* gg=L+LRA+n*16; const float* NO=L+LNOR+n*9;
            f += gg[0]*O[t*3]+gg[1]*O[t*3+1]+gg[2]*O[t*3+2];
            f += gg[3]*NO[t*3]+gg[4]*NO[t*3+1]+gg[5]*NO[t*3+2];
        }
        if (wr) out[(size_t)batch*3+t]=f;
    }
    if (t >= 4 && t < 13){
        int a=(t-4)/3, bb=(t-4)%3; float g2=0.f;
        for (int n=0;n<NN;n++){
            const float* gg=L+LRA+n*16; const float* NO=L+LNOR+n*9;
            g2 += L[LNDN+n*3+a]*gg[bb];
            g2 += gg[6+3*bb+0]*NO[a*3+0]+gg[6+3*bb+1]*NO[a*3+1]+gg[6+3*bb+2]*NO[a*3+2];
        }
        L[LGO+a*3+bb]=g2;
    }
    __syncwarp();
    if (t==0 && wr){
        const float* gO=L+LGO; const float* O=L+LSO;
        float tx=0.f,ty=0.f,tz=0.f;
        #pragma unroll
        for (int c=0;c<3;c++){
            float u0=gO[c],u1=gO[3+c],u2=gO[6+c];
            float v0=O[c], v1=O[3+c], v2=O[6+c];
            tx += u1*v2-u2*v1; ty += u2*v0-u0*v2; tz += u0*v1-u1*v0;
        }
        out[(size_t)3*B+(size_t)batch*3+0]=tx;
        out[(size_t)3*B+(size_t)batch*3+1]=ty;
        out[(size_t)3*B+(size_t)batch*3+2]=tz;
    }
}

extern "C" void kernel_launch(void* const* d_in, const int* in_sizes, int n_in,
                              void* d_out, int out_size) {
    const float* dr  = (const float*)d_in[0];
    const float* ori = (const float*)d_in[1];
    const float* nor = (const float*)d_in[2];
    const float* W0  = (const float*)d_in[3];
    const float* b0  = (const float*)d_in[4];
    const float* W1  = (const float*)d_in[5];
    const float* b1  = (const float*)d_in[6];
    const float* W2  = (const float*)d_in[7];
    const float* b2  = (const float*)d_in[8];
    const float* f1  = (const float*)d_in[9];
    const float* f2  = (const float*)d_in[10];
    float* out = (float*)d_out;

    int B = in_sizes[0] / (NBC * 3);
    int blocks = (B + LPB - 1) / LPB;
    size_t shmem = (size_t)SMEM_FLOATS * sizeof(float);
    cudaFuncSetAttribute(ep_kernel, cudaFuncAttributeMaxDynamicSharedMemorySize, (int)shmem);
    ep_kernel<<<blocks, TPB, shmem>>>(dr, ori, nor, W0, b0, W1, b1, W2, b2, f1, f2, out, B);
}

// round 16
// speedup vs baseline: 2.5139x; 1.1302x over previous
#include <cuda_runtime.h>
#include <cuda_fp16.h>
#include <math.h>

#define EPSF 1e-8f
#define NBC 64
#define NN 20
#define LPB 24
#define TPB (LPB*32)

// block weights (floats)
static constexpr int OW2=0, OB0=64, OB1=128, OMISC=192,
    OW0T=200,    // fp16 W0^T [j=64][24h] = 768 fl
    OW0T4=968,   // fp16 W0 [i=16][72h] = 576 fl
    OW1H=1544,   // fp16 W1 [k][j] stride 72h = 2304 fl
    OW1HT=3848,  // fp16 W1^T [j][k] stride 72h = 2304 fl
    WFL=6152;
// per-lane (floats)
static constexpr int LNDN=0, LNOR=60, LNEWR=240, LP=240, LFCR=260, LGO=260, LSO=280,
    LZ=292, LENC=LZ, LGZ=316, LGPRE=340, LSC=360,
    LRA=368, LDRW=368, LRR=560, LSEL=624,    // region A: DRW/RR/SEL -> featH -> GA2 -> GF
    LRB=1232, LANE_F=2096;                    // region B: h1T fp16 -> ga1 fp16 in-place
static constexpr int SMEM_FLOATS = WFL + LPB*LANE_F;   // 56456 fl = 225824 B

typedef unsigned int u32;
__device__ __forceinline__ float ex2a(float x){ float r; asm("ex2.approx.f32 %0, %1;":"=f"(r):"f"(x)); return r; }
__device__ __forceinline__ float lg2a(float x){ float r; asm("lg2.approx.f32 %0, %1;":"=f"(r):"f"(x)); return r; }
__device__ __forceinline__ float rcpa(float x){ float r; asm("rcp.approx.f32 %0, %1;":"=f"(r):"f"(x)); return r; }
__device__ __forceinline__ float tanhfst(float x){
    float e = ex2a(x * 2.885390082f);
    return fmaf(-2.0f, rcpa(e + 1.0f), 1.0f);
}
__device__ __forceinline__ float tanha(float x){
    float r; asm("tanh.approx.f32 %0, %1;":"=f"(r):"f"(x)); return r;
}
__device__ __forceinline__ void hmma(float&d0,float&d1,float&d2,float&d3,
                                     u32 a0,u32 a1,u32 a2,u32 a3,u32 b0,u32 b1){
    asm volatile("mma.sync.aligned.m16n8k16.row.col.f32.f16.f16.f32 "
                 "{%0,%1,%2,%3},{%4,%5,%6,%7},{%8,%9},{%0,%1,%2,%3};"
                 : "+f"(d0),"+f"(d1),"+f"(d2),"+f"(d3)
                 : "r"(a0),"r"(a1),"r"(a2),"r"(a3),"r"(b0),"r"(b1));
}

__global__ __launch_bounds__(TPB, 1)
void ep_kernel(const float* __restrict__ dr, const float* __restrict__ orientation,
               const float* __restrict__ n_or,
               const float* __restrict__ W0, const float* __restrict__ b0,
               const float* __restrict__ W1, const float* __restrict__ b1,
               const float* __restrict__ W2, const float* __restrict__ b2,
               const float* __restrict__ f1, const float* __restrict__ f2,
               float* __restrict__ out, int B)
{
    extern __shared__ float sm[];
    const int tid = threadIdx.x;
    for (int idx=tid; idx<768; idx+=TPB) ((u32*)(sm+OW0T))[idx]=0u;
    for (int idx=tid; idx<576; idx+=TPB) ((u32*)(sm+OW0T4))[idx]=0u;
    __syncthreads();
    {
        __half* w0t  = (__half*)(sm+OW0T);
        __half* w0t4 = (__half*)(sm+OW0T4);
        for (int idx=tid; idx<960; idx+=TPB){
            int i=idx>>6, j=idx&63; __half hv=__float2half(W0[idx]);
            w0t[j*24+i]=hv; w0t4[i*72+j]=hv;
        }
        __half* w1h  = (__half*)(sm+OW1H);
        __half* w1ht = (__half*)(sm+OW1HT);
        for (int idx=tid; idx<4096; idx+=TPB){
            int k=idx>>6, j=idx&63; __half hv=__float2half(W1[idx]);
            w1h[k*72+j]=hv; w1ht[j*72+k]=hv;
        }
    }
    if (tid < 64) { sm[OW2+tid]=W2[tid]; sm[OB0+tid]=b0[tid]; sm[OB1+tid]=b1[tid]; }
    if (tid == 0) {
        sm[OMISC] = b2[0];
        #pragma unroll
        for (int j = 0; j < 3; j++) {
            float a=f1[j]; sm[OMISC+1+j]=a*a+EPSF;
            float p=f2[j]; sm[OMISC+4+j]=p*p+EPSF;
        }
    }
    __syncthreads();

    const u32* W1h32  = (const u32*)(sm+OW1H);
    const u32* W1hT32 = (const u32*)(sm+OW1HT);
    const u32* W0T32  = (const u32*)(sm+OW0T);
    const u32* WT4_32 = (const u32*)(sm+OW0T4);

    const int li = tid >> 5, t = tid & 31;
    const int g = t >> 2, tg = t & 3;
    const int batch0 = blockIdx.x * LPB + li;
    const bool wr = batch0 < B;
    const int batch = wr ? batch0 : 0;
    float* L = sm + WFL + li * LANE_F;
    int* selp = (int*)(L + LSEL);
    __half* H1Th = (__half*)(L + LRB);
    u32*    H1T32 = (u32*)(L + LRB);
    __half* GA2h = (__half*)(L + LRA);
    const u32* GA2_32 = (const u32*)(L + LRA);

    // A: stage dr + orientation
    {
        const float4* src = (const float4*)(dr + (size_t)batch * 192);
        float4* dst = (float4*)(L + LDRW);
        dst[t] = src[t];
        if (t < 16) dst[t+32] = src[t+32];
        if (t < 9) L[LSO+t] = orientation[(size_t)batch*9 + t];
    }
    __syncwarp();
    // B: radii
    #pragma unroll
    for (int c = 0; c < 2; c++) {
        int u = 2*t+c;
        float x=L[LDRW+u*3]+EPSF, y=L[LDRW+u*3+1]+EPSF, z=L[LDRW+u*3+2]+EPSF;
        L[LRR+u] = sqrtf(x*x+y*y+z*z);
    }
    __syncwarp();
    // C: stable rank
    {
        float Ru[2]; int rk[2];
        #pragma unroll
        for (int c=0;c<2;c++){ Ru[c]=L[LRR+2*t+c]; rk[c]=0; }
        const float4* R4 = (const float4*)(L + LRR);
        #pragma unroll 4
        for (int v4=0; v4<16; v4++){
            float4 rv = R4[v4]; int v = 4*v4;
            #pragma unroll
            for (int c=0;c<2;c++){
                int u = 2*t+c;
                rk[c] += (rv.x<Ru[c])||(rv.x==Ru[c]&&v  <u);
                rk[c] += (rv.y<Ru[c])||(rv.y==Ru[c]&&v+1<u);
                rk[c] += (rv.z<Ru[c])||(rv.z==Ru[c]&&v+2<u);
                rk[c] += (rv.w<Ru[c])||(rv.w==Ru[c]&&v+3<u);
            }
        }
        #pragma unroll
        for (int c=0;c<2;c++) if (rk[c] < NN) selp[rk[c]] = 2*t+c;
    }
    __syncwarp();
    // D: gather top-20
    if (t < NN) {
        int u = selp[t];
        float Rv = L[LRR+u];
        L[LNEWR+t] = Rv;
        float inv = 1.0f / Rv;
        L[LNDN+t*3+0] = (L[LDRW+u*3+0]+EPSF)*inv;
        L[LNDN+t*3+1] = (L[LDRW+u*3+1]+EPSF)*inv;
        L[LNDN+t*3+2] = (L[LDRW+u*3+2]+EPSF)*inv;
        L[LFCR+t] = (Rv > 4.8f) ? 0.0f : (0.5f*cospif(Rv*(1.0f/4.8f)) + 0.5f);
        const float* np_ = n_or + ((size_t)batch*NBC + u)*9;
        #pragma unroll
        for (int e = 0; e < 9; e++) L[LNOR+t*9+e] = np_[e];
    }
    __syncwarp();
    // E: features -> fp16 featH [n][24h]; zero-pad first
    {
        u32* FZ = (u32*)(L+LRA);
        for (int idx=t; idx<288; idx+=32) FZ[idx]=0u;
    }
    __syncwarp();
    {
        __half* FH = (__half*)(L+LRA);
        int n = (t * 0x8889) >> 19;
        int i = t - n*15;
        #pragma unroll
        for (int it = 0; it < 10; it++) {
            int p = t + 32*it;
            if (p < 300) {
                const float* nd = L+LNDN+n*3; const float* NO = L+LNOR+n*9; const float* O = L+LSO;
                float v;
                if (i < 3)      v = nd[0]*O[i]   + nd[1]*O[3+i]   + nd[2]*O[6+i];
                else if (i < 6){ int h=i-3; v = nd[0]*NO[h] + nd[1]*NO[3+h] + nd[2]*NO[6+h]; }
                else { int l=(i-6)/3, m=(i-6)%3; v = O[l]*NO[m] + O[3+l]*NO[3+m] + O[6+l]*NO[6+m]; }
                FH[n*24+i] = __float2half(v);
            }
            n += 2; i += 2;
            if (i >= 15) { i -= 15; n += 1; }
        }
    }
    __syncwarp();

    // F: GEMM1 via mma: h1[j][n] = b0 + W0^T @ feat   (tanh.approx)
    {
        const u32* FH32 = (const u32*)(L+LRA);
        float b0g[4], b0g8[4];
        #pragma unroll
        for (int mt=0; mt<4; mt++){ b0g[mt]=sm[OB0+mt*16+g]; b0g8[mt]=sm[OB0+mt*16+g+8]; }
        float h[3][4][4];
        #pragma unroll
        for (int nt=0; nt<3; nt++)
            #pragma unroll
            for (int mt=0; mt<4; mt++){
                h[nt][mt][0]=b0g[mt]; h[nt][mt][1]=b0g[mt];
                h[nt][mt][2]=b0g8[mt]; h[nt][mt][3]=b0g8[mt];
            }
        u32 A0[4],A1[4],A2[4],A3[4];
        #pragma unroll
        for (int mt=0; mt<4; mt++){
            int ba=(mt*16+g)*12+tg;
            A0[mt]=W0T32[ba]; A1[mt]=W0T32[ba+96]; A2[mt]=W0T32[ba+4]; A3[mt]=W0T32[ba+100];
        }
        #pragma unroll
        for (int nt=0; nt<3; nt++){
            int bb=(nt*8+g)*12+tg;
            u32 bf0=FH32[bb], bf1=FH32[bb+4];
            #pragma unroll
            for (int mt=0; mt<4; mt++)
                hmma(h[nt][mt][0],h[nt][mt][1],h[nt][mt][2],h[nt][mt][3],
                     A0[mt],A1[mt],A2[mt],A3[mt],bf0,bf1);
        }
        #pragma unroll
        for (int nt=0; nt<3; nt++)
            #pragma unroll
            for (int mt=0; mt<4; mt++){
                int n0=nt*8+2*tg, j0=mt*16+g;
                H1Th[ n0   *72 + j0  ] = __float2half(tanha(h[nt][mt][0]));
                H1Th[(n0+1)*72 + j0  ] = __float2half(tanha(h[nt][mt][1]));
                H1Th[ n0   *72 + j0+8] = __float2half(tanha(h[nt][mt][2]));
                H1Th[(n0+1)*72 + j0+8] = __float2half(tanha(h[nt][mt][3]));
            }
    }
    __syncwarp();

    float b1g[4], b1g8[4], w2g[4], w2g8[4];
    #pragma unroll
    for (int mt=0; mt<4; mt++){
        b1g[mt]  = sm[OB1 + mt*16 + g];
        b1g8[mt] = sm[OB1 + mt*16 + g + 8];
        w2g[mt]  = sm[OW2 + mt*16 + g];
        w2g8[mt] = sm[OW2 + mt*16 + g + 8];
    }

    // G: GEMM2 via mma: h2 = b1 + W1^T @ h1  (tanh.approx)
    float d[3][4][4];
    #pragma unroll
    for (int nt=0; nt<3; nt++)
        #pragma unroll
        for (int mt=0; mt<4; mt++){
            d[nt][mt][0]=b1g[mt]; d[nt][mt][1]=b1g[mt];
            d[nt][mt][2]=b1g8[mt]; d[nt][mt][3]=b1g8[mt];
        }
    #pragma unroll
    for (int kt=0; kt<4; kt++){
        u32 A0[4],A1[4],A2[4],A3[4];
        #pragma unroll
        for (int mt=0; mt<4; mt++){
            int base = (mt*16+g)*36 + kt*8 + tg;
            A0[mt]=W1hT32[base];   A1[mt]=W1hT32[base+288];
            A2[mt]=W1hT32[base+4]; A3[mt]=W1hT32[base+292];
        }
        #pragma unroll
        for (int nt=0; nt<3; nt++){
            int bb = (nt*8+g)*36 + kt*8 + tg;
            u32 bf0 = H1T32[bb], bf1 = H1T32[bb+4];
            #pragma unroll
            for (int mt=0; mt<4; mt++)
                hmma(d[nt][mt][0],d[nt][mt][1],d[nt][mt][2],d[nt][mt][3],
                     A0[mt],A1[mt],A2[mt],A3[mt],bf0,bf1);
        }
    }
    #pragma unroll
    for (int nt=0; nt<3; nt++)
        #pragma unroll
        for (int mt=0; mt<4; mt++)
            #pragma unroll
            for (int c=0;c<4;c++) d[nt][mt][c] = tanha(d[nt][mt][c]);

    // H1: z[n] via fragment butterfly
    {
        float zp0[3], zp1[3];
        #pragma unroll
        for (int nt=0; nt<3; nt++){
            float p0=0.f, p1=0.f;
            #pragma unroll
            for (int mt=0; mt<4; mt++){
                p0 += w2g[mt]*d[nt][mt][0] + w2g8[mt]*d[nt][mt][2];
                p1 += w2g[mt]*d[nt][mt][1] + w2g8[mt]*d[nt][mt][3];
            }
            zp0[nt]=p0; zp1[nt]=p1;
        }
        #pragma unroll
        for (int m=4;m<32;m<<=1){
            #pragma unroll
            for (int nt=0; nt<3; nt++){
                zp0[nt] += __shfl_xor_sync(0xffffffffu, zp0[nt], m);
                zp1[nt] += __shfl_xor_sync(0xffffffffu, zp1[nt], m);
            }
        }
        if (g==0){
            float b2v = sm[OMISC];
            #pragma unroll
            for (int nt=0; nt<3; nt++){
                float2 v; v.x = zp0[nt]+b2v; v.y = zp1[nt]+b2v;
                *(float2*)(L + LZ + nt*8 + 2*tg) = v;
            }
        }
    }
    __syncwarp();
    // H2: enc, prior per n (accurate tanh)
    if (t < NN){
        float enc = tanhfst(L[LZ+t]);
        float e = enc*enc + EPSF;
        float Rm = L[LNEWR+t] - e;
        float P=0.f, D=0.f;
        #pragma unroll
        for (int j=0;j<3;j++){
            float a=sm[OMISC+1+j], p=sm[OMISC+4+j];
            float tt = ex2a(-p * lg2a(a*Rm));
            P += tt; D += p*tt;
        }
        L[LP+t]=P; L[LGPRE+t]=D/Rm; L[LENC+t]=enc;
    }
    __syncwarp();
    if (t==0){
        float S=0.f, F=0.f;
        #pragma unroll
        for (int n=0;n<NN;n++){ S+=L[LP+n]; F+=L[LFCR+n]; }
        L[LSC]=S; L[LSC+1]=F;
    }
    __syncwarp();
    if (t < NN){
        float enc=L[LENC+t];
        L[LGZ+t] = L[LSC+1]*L[LGPRE+t]*2.f*enc*(1.f-enc*enc);
        if (wr) out[(size_t)6*B + (size_t)batch*NN + t] = L[LSC]*L[LFCR+t];
    } else if (t < 24) {
        L[LGZ+t] = 0.f;
    }
    __syncwarp();
    // I: ga2 -> fp16 [n][j] stride 72
    #pragma unroll
    for (int nt=0; nt<3; nt++){
        float2 gz2 = *(const float2*)(L + LGZ + nt*8 + 2*tg);
        int n0 = nt*8 + 2*tg;
        #pragma unroll
        for (int mt=0; mt<4; mt++){
            int j0 = mt*16 + g;
            float v00 = gz2.x * w2g[mt]  * (1.f - d[nt][mt][0]*d[nt][mt][0]);
            float v01 = gz2.y * w2g[mt]  * (1.f - d[nt][mt][1]*d[nt][mt][1]);
            float v02 = gz2.x * w2g8[mt] * (1.f - d[nt][mt][2]*d[nt][mt][2]);
            float v03 = gz2.y * w2g8[mt] * (1.f - d[nt][mt][3]*d[nt][mt][3]);
            GA2h[ n0   *72 + j0  ] = __float2half(v00);
            GA2h[(n0+1)*72 + j0  ] = __float2half(v01);
            GA2h[ n0   *72 + j0+8] = __float2half(v02);
            GA2h[(n0+1)*72 + j0+8] = __float2half(v03);
        }
    }
    __syncwarp();
    // J: GEMM3 via mma: gh1[k][n] = W1 @ ga2
    float e3[3][4][4];
    #pragma unroll
    for (int nt=0; nt<3; nt++)
        #pragma unroll
        for (int mt=0; mt<4; mt++)
            #pragma unroll
            for (int c=0;c<4;c++) e3[nt][mt][c]=0.f;
    #pragma unroll
    for (int kt=0; kt<4; kt++){
        u32 A0[4],A1[4],A2[4],A3[4];
        #pragma unroll
        for (int mt=0; mt<4; mt++){
            int base = (mt*16+g)*36 + kt*8 + tg;
            A0[mt]=W1h32[base];   A1[mt]=W1h32[base+288];
            A2[mt]=W1h32[base+4]; A3[mt]=W1h32[base+292];
        }
        #pragma unroll
        for (int nt=0; nt<3; nt++){
            int bb = (nt*8+g)*36 + kt*8 + tg;
            u32 bf0 = GA2_32[bb], bf1 = GA2_32[bb+4];
            #pragma unroll
            for (int mt=0; mt<4; mt++)
                hmma(e3[nt][mt][0],e3[nt][mt][1],e3[nt][mt][2],e3[nt][mt][3],
                     A0[mt],A1[mt],A2[mt],A3[mt],bf0,bf1);
        }
    }
    // ga1 = gh1*(1-h1^2) fp16, IN-PLACE over h1T
    #pragma unroll
    for (int nt=0; nt<3; nt++){
        int n0 = nt*8 + 2*tg;
        if (n0 < 20){
            #pragma unroll
            for (int mt=0; mt<4; mt++){
                int k = mt*16 + g;
                int ix = n0*72 + k;
                float hv = __half2float(H1Th[ix]);
                H1Th[ix] = __float2half(e3[nt][mt][0]*(1.f-hv*hv));
                ix = (n0+1)*72 + k;
                hv = __half2float(H1Th[ix]);
                H1Th[ix] = __float2half(e3[nt][mt][1]*(1.f-hv*hv));
                ix = n0*72 + k + 8;
                hv = __half2float(H1Th[ix]);
                H1Th[ix] = __float2half(e3[nt][mt][2]*(1.f-hv*hv));
                ix = (n0+1)*72 + k + 8;
                hv = __half2float(H1Th[ix]);
                H1Th[ix] = __float2half(e3[nt][mt][3]*(1.f-hv*hv));
            }
        }
    }
    __syncwarp();
    // K: GEMM4 via mma: gfeat[n][i] = ga1^T @ W0^T
    {
        const u32* GA1_32 = (const u32*)(L+LRB);
        float gf[2][2][4];
        #pragma unroll
        for (int nt=0; nt<2; nt++)
            #pragma unroll
            for (int mt=0; mt<2; mt++)
                #pragma unroll
                for (int c=0;c<4;c++) gf[nt][mt][c]=0.f;
        #pragma unroll
        for (int kt=0; kt<4; kt++){
            u32 A0[2],A1[2],A2[2],A3[2];
            #pragma unroll
            for (int mt=0; mt<2; mt++){
                int ba = (mt*8+g)*36 + kt*8 + tg;
                A0[mt]=GA1_32[ba];   A1[mt]=GA1_32[ba+288];
                A2[mt]=GA1_32[ba+4]; A3[mt]=GA1_32[ba+292];
            }
            #pragma unroll
            for (int nt=0; nt<2; nt++){
                int bb = (nt*8+g)*36 + kt*8 + tg;
                u32 bf0 = WT4_32[bb], bf1 = WT4_32[bb+4];
                #pragma unroll
                for (int mt=0; mt<2; mt++)
                    hmma(gf[nt][mt][0],gf[nt][mt][1],gf[nt][mt][2],gf[nt][mt][3],
                         A0[mt],A1[mt],A2[mt],A3[mt],bf0,bf1);
            }
        }
        float* GF = L + LRA;
        #pragma unroll
        for (int nt=0; nt<2; nt++){
            int i0 = nt*8 + 2*tg;
            GF[ g    *16 + i0  ] = gf[nt][0][0];
            GF[ g    *16 + i0+1] = gf[nt][0][1];
            GF[(g+8) *16 + i0  ] = gf[nt][0][2];
            GF[(g+8) *16 + i0+1] = gf[nt][0][3];
            if (g < 4){
                GF[(16+g)*16 + i0  ] = gf[nt][1][2];
                GF[(16+g)*16 + i0+1] = gf[nt][1][3];
            }
        }
    }
    __syncwarp();
    // L: force, gO, torque
    if (t < 3){
        float f=0.f; const float* O=L+LSO;
        for (int n=0;n<NN;n++){
            const float* gg=L+LRA+n*16; const float* NO=L+LNOR+n*9;
            f += gg[0]*O[t*3]+gg[1]*O[t*3+1]+gg[2]*O[t*3+2];
            f += gg[3]*NO[t*3]+gg[4]*NO[t*3+1]+gg[5]*NO[t*3+2];
        }
        if (wr) out[(size_t)batch*3+t]=f;
    }
    if (t >= 4 && t < 13){
        int a=(t-4)/3, bb=(t-4)%3; float g2=0.f;
        for (int n=0;n<NN;n++){
            const float* gg=L+LRA+n*16; const float* NO=L+LNOR+n*9;
            g2 += L[LNDN+n*3+a]*gg[bb];
            g2 += gg[6+3*bb+0]*NO[a*3+0]+gg[6+3*bb+1]*NO[a*3+1]+gg[6+3*bb+2]*NO[a*3+2];
        }
        L[LGO+a*3+bb]=g2;
    }
    __syncwarp();
    if (t==0 && wr){
        const float* gO=L+LGO; const float* O=L+LSO;
        float tx=0.f,ty=0.f,tz=0.f;
        #pragma unroll
        for (int c=0;c<3;c++){
            float u0=gO[c],u1=gO[3+c],u2=gO[6+c];
            float v0=O[c], v1=O[3+c], v2=O[6+c];
            tx += u1*v2-u2*v1; ty += u2*v0-u0*v2; tz += u0*v1-u1*v0;
        }
        out[(size_t)3*B+(size_t)batch*3+0]=tx;
        out[(size_t)3*B+(size_t)batch*3+1]=ty;
        out[(size_t)3*B+(size_t)batch*3+2]=tz;
    }
}

extern "C" void kernel_launch(void* const* d_in, const int* in_sizes, int n_in,
                              void* d_out, int out_size) {
    const float* dr  = (const float*)d_in[0];
    const float* ori = (const float*)d_in[1];
    const float* nor = (const float*)d_in[2];
    const float* W0  = (const float*)d_in[3];
    const float* b0  = (const float*)d_in[4];
    const float* W1  = (const float*)d_in[5];
    const float* b1  = (const float*)d_in[6];
    const float* W2  = (const float*)d_in[7];
    const float* b2  = (const float*)d_in[8];
    const float* f1  = (const float*)d_in[9];
    const float* f2  = (const float*)d_in[10];
    float* out = (float*)d_out;

    int B = in_sizes[0] / (NBC * 3);
    int blocks = (B + LPB - 1) / LPB;
    size_t shmem = (size_t)SMEM_FLOATS * sizeof(float);
    cudaFuncSetAttribute(ep_kernel, cudaFuncAttributeMaxDynamicSharedMemorySize, (int)shmem);
    ep_kernel<<<blocks, TPB, shmem>>>(dr, ori, nor, W0, b0, W1, b1, W2, b2, f1, f2, out, B);
}

// round 17
// speedup vs baseline: 2.6463x; 1.0527x over previous
#include <cuda_runtime.h>
#include <cuda_fp16.h>
#include <math.h>

#define EPSF 1e-8f
#define NBC 64
#define NN 20
#define LPB 24
#define TPB (LPB*32)

// block weights (floats)
static constexpr int OW2=0, OB0=64, OB1=128, OMISC=192,
    OW0T=200, OW0T4=968, OW1H=1544, OW1HT=3848, WFL=6152;
// per-lane (floats)
static constexpr int LNDN=0, LNOR=60, LNEWR=240, LP=240, LFCR=260, LGO=260, LSO=280,
    LZ=292, LENC=LZ, LGZ=316, LGPRE=340, LSC=360,
    LRA=368, LDRW=368, LRR=560, LKEY=624, LSEL=688,  // region A: DRW/RR/KEY/SEL -> featH -> GA2 -> GF
    LRB=1232, LANE_F=2096;                            // region B: h1T fp16 -> ga1 fp16 in-place
static constexpr int SMEM_FLOATS = WFL + LPB*LANE_F;   // 56456 fl = 225824 B

typedef unsigned int u32;
__device__ __forceinline__ float ex2a(float x){ float r; asm("ex2.approx.f32 %0, %1;":"=f"(r):"f"(x)); return r; }
__device__ __forceinline__ float lg2a(float x){ float r; asm("lg2.approx.f32 %0, %1;":"=f"(r):"f"(x)); return r; }
__device__ __forceinline__ float rcpa(float x){ float r; asm("rcp.approx.f32 %0, %1;":"=f"(r):"f"(x)); return r; }
__device__ __forceinline__ float tanhfst(float x){
    float e = ex2a(x * 2.885390082f);
    return fmaf(-2.0f, rcpa(e + 1.0f), 1.0f);
}
__device__ __forceinline__ float tanha(float x){
    float r; asm("tanh.approx.f32 %0, %1;":"=f"(r):"f"(x)); return r;
}
__device__ __forceinline__ u32 pack_f16x2(float lo, float hi){
    u32 r; asm("cvt.rn.f16x2.f32 %0, %1, %2;" : "=r"(r) : "f"(hi), "f"(lo)); return r;
}
__device__ __forceinline__ void hmma(float&d0,float&d1,float&d2,float&d3,
                                     u32 a0,u32 a1,u32 a2,u32 a3,u32 b0,u32 b1){
    asm volatile("mma.sync.aligned.m16n8k16.row.col.f32.f16.f16.f32 "
                 "{%0,%1,%2,%3},{%4,%5,%6,%7},{%8,%9},{%0,%1,%2,%3};"
                 : "+f"(d0),"+f"(d1),"+f"(d2),"+f"(d3)
                 : "r"(a0),"r"(a1),"r"(a2),"r"(a3),"r"(b0),"r"(b1));
}

__global__ __launch_bounds__(TPB, 1)
void ep_kernel(const float* __restrict__ dr, const float* __restrict__ orientation,
               const float* __restrict__ n_or,
               const float* __restrict__ W0, const float* __restrict__ b0,
               const float* __restrict__ W1, const float* __restrict__ b1,
               const float* __restrict__ W2, const float* __restrict__ b2,
               const float* __restrict__ f1, const float* __restrict__ f2,
               float* __restrict__ out, int B)
{
    extern __shared__ float sm[];
    const int tid = threadIdx.x;
    for (int idx=tid; idx<768; idx+=TPB) ((u32*)(sm+OW0T))[idx]=0u;
    for (int idx=tid; idx<576; idx+=TPB) ((u32*)(sm+OW0T4))[idx]=0u;
    __syncthreads();
    {
        __half* w0t  = (__half*)(sm+OW0T);
        __half* w0t4 = (__half*)(sm+OW0T4);
        for (int idx=tid; idx<960; idx+=TPB){
            int i=idx>>6, j=idx&63; __half hv=__float2half(W0[idx]);
            w0t[j*24+i]=hv; w0t4[i*72+j]=hv;
        }
        __half* w1h  = (__half*)(sm+OW1H);
        __half* w1ht = (__half*)(sm+OW1HT);
        for (int idx=tid; idx<4096; idx+=TPB){
            int k=idx>>6, j=idx&63; __half hv=__float2half(W1[idx]);
            w1h[k*72+j]=hv; w1ht[j*72+k]=hv;
        }
    }
    if (tid < 64) { sm[OW2+tid]=W2[tid]; sm[OB0+tid]=b0[tid]; sm[OB1+tid]=b1[tid]; }
    if (tid == 0) {
        sm[OMISC] = b2[0];
        #pragma unroll
        for (int j = 0; j < 3; j++) {
            float a=f1[j]; sm[OMISC+1+j]=a*a+EPSF;
            float p=f2[j]; sm[OMISC+4+j]=p*p+EPSF;
        }
    }
    __syncthreads();

    const u32* W1h32  = (const u32*)(sm+OW1H);
    const u32* W1hT32 = (const u32*)(sm+OW1HT);
    const u32* W0T32  = (const u32*)(sm+OW0T);
    const u32* WT4_32 = (const u32*)(sm+OW0T4);

    const int li = tid >> 5, t = tid & 31;
    const int g = t >> 2, tg = t & 3;
    const int batch0 = blockIdx.x * LPB + li;
    const bool wr = batch0 < B;
    const int batch = wr ? batch0 : 0;
    float* L = sm + WFL + li * LANE_F;
    int* selp = (int*)(L + LSEL);
    u32* KY = (u32*)(L + LKEY);
    __half* H1Th = (__half*)(L + LRB);
    u32*    H1T32 = (u32*)(L + LRB);
    __half* GA2h = (__half*)(L + LRA);
    const u32* GA2_32 = (const u32*)(L + LRA);

    // A: stage dr + orientation
    {
        const float4* src = (const float4*)(dr + (size_t)batch * 192);
        float4* dst = (float4*)(L + LDRW);
        dst[t] = src[t];
        if (t < 16) dst[t+32] = src[t+32];
        if (t < 9) L[LSO+t] = orientation[(size_t)batch*9 + t];
    }
    __syncwarp();
    // B: radii + monotone 32-bit sort keys ((bits(R)-bits(1.0))<<6 | idx)
    u32 myK[2];
    #pragma unroll
    for (int c = 0; c < 2; c++) {
        int u = 2*t+c;
        float x=L[LDRW+u*3]+EPSF, y=L[LDRW+u*3+1]+EPSF, z=L[LDRW+u*3+2]+EPSF;
        float Rv = sqrtf(x*x+y*y+z*z);
        L[LRR+u] = Rv;
        u32 k = ((__float_as_uint(Rv) - 0x3F800000u) << 6) | (u32)u;
        KY[u] = k; myK[c] = k;
    }
    __syncwarp();
    // C: stable rank via single u32 compares
    {
        int rk0=0, rk1=0;
        const uint4* K4 = (const uint4*)KY;
        #pragma unroll 4
        for (int q=0; q<16; q++){
            uint4 kv = K4[q];
            rk0 += (kv.x<myK[0]) + (kv.y<myK[0]) + (kv.z<myK[0]) + (kv.w<myK[0]);
            rk1 += (kv.x<myK[1]) + (kv.y<myK[1]) + (kv.z<myK[1]) + (kv.w<myK[1]);
        }
        if (rk0 < NN) selp[rk0] = 2*t;
        if (rk1 < NN) selp[rk1] = 2*t+1;
    }
    __syncwarp();
    // D: gather top-20
    if (t < NN) {
        int u = selp[t];
        float Rv = L[LRR+u];
        L[LNEWR+t] = Rv;
        float inv = 1.0f / Rv;
        L[LNDN+t*3+0] = (L[LDRW+u*3+0]+EPSF)*inv;
        L[LNDN+t*3+1] = (L[LDRW+u*3+1]+EPSF)*inv;
        L[LNDN+t*3+2] = (L[LDRW+u*3+2]+EPSF)*inv;
        L[LFCR+t] = (Rv > 4.8f) ? 0.0f : (0.5f*cospif(Rv*(1.0f/4.8f)) + 0.5f);
        const float* np_ = n_or + ((size_t)batch*NBC + u)*9;
        #pragma unroll
        for (int e = 0; e < 9; e++) L[LNOR+t*9+e] = np_[e];
    }
    __syncwarp();
    // E: features -> fp16 featH [n][24h]; zero-pad first
    {
        u32* FZ = (u32*)(L+LRA);
        for (int idx=t; idx<288; idx+=32) FZ[idx]=0u;
    }
    __syncwarp();
    {
        __half* FH = (__half*)(L+LRA);
        int n = (t * 0x8889) >> 19;
        int i = t - n*15;
        #pragma unroll
        for (int it = 0; it < 10; it++) {
            int p = t + 32*it;
            if (p < 300) {
                const float* nd = L+LNDN+n*3; const float* NO = L+LNOR+n*9; const float* O = L+LSO;
                float v;
                if (i < 3)      v = nd[0]*O[i]   + nd[1]*O[3+i]   + nd[2]*O[6+i];
                else if (i < 6){ int h=i-3; v = nd[0]*NO[h] + nd[1]*NO[3+h] + nd[2]*NO[6+h]; }
                else { int l=(i-6)/3, m=(i-6)%3; v = O[l]*NO[m] + O[3+l]*NO[3+m] + O[6+l]*NO[6+m]; }
                FH[n*24+i] = __float2half(v);
            }
            n += 2; i += 2;
            if (i >= 15) { i -= 15; n += 1; }
        }
    }
    __syncwarp();

    // F: GEMM1 via mma: h1[j][n] = b0 + W0^T @ feat  (tanh.approx f32, packed cvt)
    {
        const u32* FH32 = (const u32*)(L+LRA);
        float b0g[4], b0g8[4];
        #pragma unroll
        for (int mt=0; mt<4; mt++){ b0g[mt]=sm[OB0+mt*16+g]; b0g8[mt]=sm[OB0+mt*16+g+8]; }
        float h[3][4][4];
        #pragma unroll
        for (int nt=0; nt<3; nt++)
            #pragma unroll
            for (int mt=0; mt<4; mt++){
                h[nt][mt][0]=b0g[mt]; h[nt][mt][1]=b0g[mt];
                h[nt][mt][2]=b0g8[mt]; h[nt][mt][3]=b0g8[mt];
            }
        u32 A0[4],A1[4],A2[4],A3[4];
        #pragma unroll
        for (int mt=0; mt<4; mt++){
            int ba=(mt*16+g)*12+tg;
            A0[mt]=W0T32[ba]; A1[mt]=W0T32[ba+96]; A2[mt]=W0T32[ba+4]; A3[mt]=W0T32[ba+100];
        }
        #pragma unroll
        for (int nt=0; nt<3; nt++){
            int bb=(nt*8+g)*12+tg;
            u32 bf0=FH32[bb], bf1=FH32[bb+4];
            #pragma unroll
            for (int mt=0; mt<4; mt++)
                hmma(h[nt][mt][0],h[nt][mt][1],h[nt][mt][2],h[nt][mt][3],
                     A0[mt],A1[mt],A2[mt],A3[mt],bf0,bf1);
        }
        #pragma unroll
        for (int nt=0; nt<3; nt++)
            #pragma unroll
            for (int mt=0; mt<4; mt++){
                int n0=nt*8+2*tg, j0=mt*16+g;
                u32 pa = pack_f16x2(tanha(h[nt][mt][0]), tanha(h[nt][mt][1]));
                __half2 ha = *(__half2*)&pa;
                H1Th[ n0   *72 + j0  ] = __low2half(ha);
                H1Th[(n0+1)*72 + j0  ] = __high2half(ha);
                u32 pb = pack_f16x2(tanha(h[nt][mt][2]), tanha(h[nt][mt][3]));
                __half2 hb = *(__half2*)&pb;
                H1Th[ n0   *72 + j0+8] = __low2half(hb);
                H1Th[(n0+1)*72 + j0+8] = __high2half(hb);
            }
    }
    __syncwarp();

    float b1g[4], b1g8[4], w2g[4], w2g8[4];
    #pragma unroll
    for (int mt=0; mt<4; mt++){
        b1g[mt]  = sm[OB1 + mt*16 + g];
        b1g8[mt] = sm[OB1 + mt*16 + g + 8];
        w2g[mt]  = sm[OW2 + mt*16 + g];
        w2g8[mt] = sm[OW2 + mt*16 + g + 8];
    }

    // G: GEMM2 via mma: h2 = b1 + W1^T @ h1  (tanh.approx f32)
    float d[3][4][4];
    #pragma unroll
    for (int nt=0; nt<3; nt++)
        #pragma unroll
        for (int mt=0; mt<4; mt++){
            d[nt][mt][0]=b1g[mt]; d[nt][mt][1]=b1g[mt];
            d[nt][mt][2]=b1g8[mt]; d[nt][mt][3]=b1g8[mt];
        }
    #pragma unroll
    for (int kt=0; kt<4; kt++){
        u32 A0[4],A1[4],A2[4],A3[4];
        #pragma unroll
        for (int mt=0; mt<4; mt++){
            int base = (mt*16+g)*36 + kt*8 + tg;
            A0[mt]=W1hT32[base];   A1[mt]=W1hT32[base+288];
            A2[mt]=W1hT32[base+4]; A3[mt]=W1hT32[base+292];
        }
        #pragma unroll
        for (int nt=0; nt<3; nt++){
            int bb = (nt*8+g)*36 + kt*8 + tg;
            u32 bf0 = H1T32[bb], bf1 = H1T32[bb+4];
            #pragma unroll
            for (int mt=0; mt<4; mt++)
                hmma(d[nt][mt][0],d[nt][mt][1],d[nt][mt][2],d[nt][mt][3],
                     A0[mt],A1[mt],A2[mt],A3[mt],bf0,bf1);
        }
    }
    #pragma unroll
    for (int nt=0; nt<3; nt++)
        #pragma unroll
        for (int mt=0; mt<4; mt++)
            #pragma unroll
            for (int c=0;c<4;c++) d[nt][mt][c] = tanha(d[nt][mt][c]);

    // H1: z[n] via fragment butterfly
    {
        float zp0[3], zp1[3];
        #pragma unroll
        for (int nt=0; nt<3; nt++){
            float p0=0.f, p1=0.f;
            #pragma unroll
            for (int mt=0; mt<4; mt++){
                p0 += w2g[mt]*d[nt][mt][0] + w2g8[mt]*d[nt][mt][2];
                p1 += w2g[mt]*d[nt][mt][1] + w2g8[mt]*d[nt][mt][3];
            }
            zp0[nt]=p0; zp1[nt]=p1;
        }
        #pragma unroll
        for (int m=4;m<32;m<<=1){
            #pragma unroll
            for (int nt=0; nt<3; nt++){
                zp0[nt] += __shfl_xor_sync(0xffffffffu, zp0[nt], m);
                zp1[nt] += __shfl_xor_sync(0xffffffffu, zp1[nt], m);
            }
        }
        if (g==0){
            float b2v = sm[OMISC];
            #pragma unroll
            for (int nt=0; nt<3; nt++){
                float2 v; v.x = zp0[nt]+b2v; v.y = zp1[nt]+b2v;
                *(float2*)(L + LZ + nt*8 + 2*tg) = v;
            }
        }
    }
    __syncwarp();
    // H2: enc, prior per n (accurate tanh)
    if (t < NN){
        float enc = tanhfst(L[LZ+t]);
        float e = enc*enc + EPSF;
        float Rm = L[LNEWR+t] - e;
        float P=0.f, D=0.f;
        #pragma unroll
        for (int j=0;j<3;j++){
            float a=sm[OMISC+1+j], p=sm[OMISC+4+j];
            float tt = ex2a(-p * lg2a(a*Rm));
            P += tt; D += p*tt;
        }
        L[LP+t]=P; L[LGPRE+t]=D/Rm; L[LENC+t]=enc;
    }
    __syncwarp();
    if (t==0){
        float S=0.f, F=0.f;
        #pragma unroll
        for (int n=0;n<NN;n++){ S+=L[LP+n]; F+=L[LFCR+n]; }
        L[LSC]=S; L[LSC+1]=F;
    }
    __syncwarp();
    if (t < NN){
        float enc=L[LENC+t];
        L[LGZ+t] = L[LSC+1]*L[LGPRE+t]*2.f*enc*(1.f-enc*enc);
        if (wr) out[(size_t)6*B + (size_t)batch*NN + t] = L[LSC]*L[LFCR+t];
    } else if (t < 24) {
        L[LGZ+t] = 0.f;
    }
    __syncwarp();
    // I: ga2 -> fp16 [n][j] stride 72 (packed cvt)
    #pragma unroll
    for (int nt=0; nt<3; nt++){
        float2 gz2 = *(const float2*)(L + LGZ + nt*8 + 2*tg);
        int n0 = nt*8 + 2*tg;
        #pragma unroll
        for (int mt=0; mt<4; mt++){
            int j0 = mt*16 + g;
            float v00 = gz2.x * w2g[mt]  * (1.f - d[nt][mt][0]*d[nt][mt][0]);
            float v01 = gz2.y * w2g[mt]  * (1.f - d[nt][mt][1]*d[nt][mt][1]);
            float v02 = gz2.x * w2g8[mt] * (1.f - d[nt][mt][2]*d[nt][mt][2]);
            float v03 = gz2.y * w2g8[mt] * (1.f - d[nt][mt][3]*d[nt][mt][3]);
            u32 pa = pack_f16x2(v00, v01);
            __half2 ha = *(__half2*)&pa;
            GA2h[ n0   *72 + j0  ] = __low2half(ha);
            GA2h[(n0+1)*72 + j0  ] = __high2half(ha);
            u32 pb = pack_f16x2(v02, v03);
            __half2 hb = *(__half2*)&pb;
            GA2h[ n0   *72 + j0+8] = __low2half(hb);
            GA2h[(n0+1)*72 + j0+8] = __high2half(hb);
        }
    }
    __syncwarp();
    // J: GEMM3 via mma: gh1[k][n] = W1 @ ga2
    float e3[3][4][4];
    #pragma unroll
    for (int nt=0; nt<3; nt++)
        #pragma unroll
        for (int mt=0; mt<4; mt++)
            #pragma unroll
            for (int c=0;c<4;c++) e3[nt][mt][c]=0.f;
    #pragma unroll
    for (int kt=0; kt<4; kt++){
        u32 A0[4],A1[4],A2[4],A3[4];
        #pragma unroll
        for (int mt=0; mt<4; mt++){
            int base = (mt*16+g)*36 + kt*8 + tg;
            A0[mt]=W1h32[base];   A1[mt]=W1h32[base+288];
            A2[mt]=W1h32[base+4]; A3[mt]=W1h32[base+292];
        }
        #pragma unroll
        for (int nt=0; nt<3; nt++){
            int bb = (nt*8+g)*36 + kt*8 + tg;
            u32 bf0 = GA2_32[bb], bf1 = GA2_32[bb+4];
            #pragma unroll
            for (int mt=0; mt<4; mt++)
                hmma(e3[nt][mt][0],e3[nt][mt][1],e3[nt][mt][2],e3[nt][mt][3],
                     A0[mt],A1[mt],A2[mt],A3[mt],bf0,bf1);
        }
    }
    // ga1 = gh1*(1-h1^2) fp16, IN-PLACE over h1T
    #pragma unroll
    for (int nt=0; nt<3; nt++){
        int n0 = nt*8 + 2*tg;
        if (n0 < 20){
            #pragma unroll
            for (int mt=0; mt<4; mt++){
                int k = mt*16 + g;
                int ix = n0*72 + k;
                float hv = __half2float(H1Th[ix]);
                H1Th[ix] = __float2half(e3[nt][mt][0]*(1.f-hv*hv));
                ix = (n0+1)*72 + k;
                hv = __half2float(H1Th[ix]);
                H1Th[ix] = __float2half(e3[nt][mt][1]*(1.f-hv*hv));
                ix = n0*72 + k + 8;
                hv = __half2float(H1Th[ix]);
                H1Th[ix] = __float2half(e3[nt][mt][2]*(1.f-hv*hv));
                ix = (n0+1)*72 + k + 8;
                hv = __half2float(H1Th[ix]);
                H1Th[ix] = __float2half(e3[nt][mt][3]*(1.f-hv*hv));
            }
        }
    }
    __syncwarp();
    // K: GEMM4 via mma: gfeat[n][i] = ga1^T @ W0^T
    {
        const u32* GA1_32 = (const u32*)(L+LRB);
        float gf[2][2][4];
        #pragma unroll
        for (int nt=0; nt<2; nt++)
            #pragma unroll
            for (int mt=0; mt<2; mt++)
                #pragma unroll
                for (int c=0;c<4;c++) gf[nt][mt][c]=0.f;
        #pragma unroll
        for (int kt=0; kt<4; kt++){
            u32 A0[2],A1[2],A2[2],A3[2];
            #pragma unroll
            for (int mt=0; mt<2; mt++){
                int ba = (mt*8+g)*36 + kt*8 + tg;
                A0[mt]=GA1_32[ba];   A1[mt]=GA1_32[ba+288];
                A2[mt]=GA1_32[ba+4]; A3[mt]=GA1_32[ba+292];
            }
            #pragma unroll
            for (int nt=0; nt<2; nt++){
                int bb = (nt*8+g)*36 + kt*8 + tg;
                u32 bf0 = WT4_32[bb], bf1 = WT4_32[bb+4];
                #pragma unroll
                for (int mt=0; mt<2; mt++)
                    hmma(gf[nt][mt][0],gf[nt][mt][1],gf[nt][mt][2],gf[nt][mt][3],
                         A0[mt],A1[mt],A2[mt],A3[mt],bf0,bf1);
            }
        }
        float* GF = L + LRA;
        #pragma unroll
        for (int nt=0; nt<2; nt++){
            int i0 = nt*8 + 2*tg;
            GF[ g    *16 + i0  ] = gf[nt][0][0];
            GF[ g    *16 + i0+1] = gf[nt][0][1];
            GF[(g+8) *16 + i0  ] = gf[nt][0][2];
            GF[(g+8) *16 + i0+1] = gf[nt][0][3];
            if (g < 4){
                GF[(16+g)*16 + i0  ] = gf[nt][1][2];
                GF[(16+g)*16 + i0+1] = gf[nt][1][3];
            }
        }
    }
    __syncwarp();
    // L: force, gO, torque
    if (t < 3){
        float f=0.f; const float* O=L+LSO;
        for (int n=0;n<NN;n++){
            const float* gg=L+LRA+n*16; const float* NO=L+LNOR+n*9;
            f += gg[0]*O[t*3]+gg[1]*O[t*3+1]+gg[2]*O[t*3+2];
            f += gg[3]*NO[t*3]+gg[4]*NO[t*3+1]+gg[5]*NO[t*3+2];
        }
        if (wr) out[(size_t)batch*3+t]=f;
    }
    if (t >= 4 && t < 13){
        int a=(t-4)/3, bb=(t-4)%3; float g2=0.f;
        for (int n=0;n<NN;n++){
            const float* gg=L+LRA+n*16; const float* NO=L+LNOR+n*9;
            g2 += L[LNDN+n*3+a]*gg[bb];
            g2 += gg[6+3*bb+0]*NO[a*3+0]+gg[6+3*bb+1]*NO[a*3+1]+gg[6+3*bb+2]*NO[a*3+2];
        }
        L[LGO+a*3+bb]=g2;
    }
    __syncwarp();
    if (t==0 && wr){
        const float* gO=L+LGO; const float* O=L+LSO;
        float tx=0.f,ty=0.f,tz=0.f;
        #pragma unroll
        for (int c=0;c<3;c++){
            float u0=gO[c],u1=gO[3+c],u2=gO[6+c];
            float v0=O[c], v1=O[3+c], v2=O[6+c];
            tx += u1*v2-u2*v1; ty += u2*v0-u0*v2; tz += u0*v1-u1*v0;
        }
        out[(size_t)3*B+(size_t)batch*3+0]=tx;
        out[(size_t)3*B+(size_t)batch*3+1]=ty;
        out[(size_t)3*B+(size_t)batch*3+2]=tz;
    }
}

extern "C" void kernel_launch(void* const* d_in, const int* in_sizes, int n_in,
                              void* d_out, int out_size) {
    const float* dr  = (const float*)d_in[0];
    const float* ori = (const float*)d_in[1];
    const float* nor = (const float*)d_in[2];
    const float* W0  = (const float*)d_in[3];
    const float* b0  = (const float*)d_in[4];
    const float* W1  = (const float*)d_in[5];
    const float* b1  = (const float*)d_in[6];
    const float* W2  = (const float*)d_in[7];
    const float* b2  = (const float*)d_in[8];
    const float* f1  = (const float*)d_in[9];
    const float* f2  = (const float*)d_in[10];
    float* out = (float*)d_out;

    int B = in_sizes[0] / (NBC * 3);
    int blocks = (B + LPB - 1) / LPB;
    size_t shmem = (size_t)SMEM_FLOATS * sizeof(float);
    cudaFuncSetAttribute(ep_kernel, cudaFuncAttributeMaxDynamicSharedMemorySize, (int)shmem);
    ep_kernel<<<blocks, TPB, shmem>>>(dr, ori, nor, W0, b0, W1, b1, W2, b2, f1, f2, out, B);
}